// round 3
// baseline (speedup 1.0000x reference)
#include <cuda_runtime.h>
#include <math.h>

// Problem dims (fixed by reference setup_inputs)
#define BB 32
#define TT 12
#define NS 325          // sensors
#define DD 128
#define HH 8
#define HD 16
#define FF 512
#define D3 384
#define MTOK (BB*TT*NS) // 124800 tokens

// ---------------- scratch (device globals; no allocation allowed) ----------
__device__ float g_qkv [(size_t)MTOK * D3];
__device__ float g_attn[(size_t)MTOK * DD];
__device__ float g_x1  [(size_t)MTOK * DD];
__device__ float g_x2  [(size_t)MTOK * DD];
__device__ float g_hid [(size_t)MTOK * FF];

__device__ __forceinline__ float gelu_f(float v) {
    // tanh-approx GELU via sigmoid identity: 0.5v(1+tanh(u)) = v*sigmoid(2u)
    const float u2 = 1.5957691216057308f * (v + 0.044715f * v * v * v);
    return v * (1.0f / (1.0f + __expf(-u2)));
}

// ---------------- NT SGEMM: C[M,N] = A[M,K] @ W[N,K]^T + bias --------------
// BM=BN=128, BK=8, 256 threads, 8x8 per-thread microtile, reg-prefetch.
// EPI: 0 = bias only, 1 = bias + GELU
template<int EPI>
__global__ __launch_bounds__(256, 2) void gemm_nt_kernel(
    const float* __restrict__ A, const float* __restrict__ W,
    const float* __restrict__ bias, float* __restrict__ C,
    int M, int N, int K)
{
    __shared__ float As[8][132];
    __shared__ float Ws[8][132];
    const int tid = threadIdx.x;
    const int tx = tid & 15;          // 0..15 -> n
    const int ty = tid >> 4;          // 0..15 -> m
    const int m0 = blockIdx.y * 128;
    const int n0 = blockIdx.x * 128;

    const int lrow = tid >> 1;        // 0..127
    const int lk   = (tid & 1) * 4;   // 0 or 4

    const float* Ag = A + (size_t)(m0 + lrow) * K + lk;
    const float* Wg = W + (size_t)(n0 + lrow) * K + lk;

    float acc[8][8];
    #pragma unroll
    for (int i = 0; i < 8; i++)
        #pragma unroll
        for (int j = 0; j < 8; j++) acc[i][j] = 0.f;

    float4 av = *(const float4*)(Ag);
    float4 wv = *(const float4*)(Wg);

    for (int k0 = 0; k0 < K; k0 += 8) {
        __syncthreads();
        As[lk+0][lrow] = av.x; As[lk+1][lrow] = av.y;
        As[lk+2][lrow] = av.z; As[lk+3][lrow] = av.w;
        Ws[lk+0][lrow] = wv.x; Ws[lk+1][lrow] = wv.y;
        Ws[lk+2][lrow] = wv.z; Ws[lk+3][lrow] = wv.w;
        __syncthreads();
        if (k0 + 8 < K) {
            av = *(const float4*)(Ag + k0 + 8);
            wv = *(const float4*)(Wg + k0 + 8);
        }
        #pragma unroll
        for (int kk = 0; kk < 8; kk++) {
            float a[8], b[8];
            float4 a0 = *(const float4*)&As[kk][ty * 8];
            float4 a1 = *(const float4*)&As[kk][ty * 8 + 4];
            float4 b0 = *(const float4*)&Ws[kk][tx * 8];
            float4 b1 = *(const float4*)&Ws[kk][tx * 8 + 4];
            a[0]=a0.x; a[1]=a0.y; a[2]=a0.z; a[3]=a0.w;
            a[4]=a1.x; a[5]=a1.y; a[6]=a1.z; a[7]=a1.w;
            b[0]=b0.x; b[1]=b0.y; b[2]=b0.z; b[3]=b0.w;
            b[4]=b1.x; b[5]=b1.y; b[6]=b1.z; b[7]=b1.w;
            #pragma unroll
            for (int i = 0; i < 8; i++)
                #pragma unroll
                for (int j = 0; j < 8; j++)
                    acc[i][j] += a[i] * b[j];
        }
    }

    float bv[8];
    #pragma unroll
    for (int j = 0; j < 8; j++) bv[j] = bias[n0 + tx * 8 + j];

    #pragma unroll
    for (int i = 0; i < 8; i++) {
        const int m = m0 + ty * 8 + i;
        float o[8];
        #pragma unroll
        for (int j = 0; j < 8; j++) {
            float v = acc[i][j] + bv[j];
            if (EPI == 1) v = gelu_f(v);
            o[j] = v;
        }
        float* cp = C + (size_t)m * N + n0 + tx * 8;
        *(float4*)(cp)     = make_float4(o[0], o[1], o[2], o[3]);
        *(float4*)(cp + 4) = make_float4(o[4], o[5], o[6], o[7]);
    }
}

// ------- NT SGEMM fused with residual + LayerNorm. N fixed at 128. --------
// out = LN(res + A@W^T + bias) * g + b.  One block row covers the full
// feature dim, so the LN reduce is a 16-lane shfl across the tx group.
__global__ __launch_bounds__(256, 2) void gemm_nt_ln_kernel(
    const float* __restrict__ A, const float* __restrict__ W,
    const float* __restrict__ bias, const float* __restrict__ res,
    const float* __restrict__ lng, const float* __restrict__ lnb,
    float* __restrict__ C, int M, int K)
{
    __shared__ float As[8][132];
    __shared__ float Ws[8][132];
    const int tid = threadIdx.x;
    const int tx = tid & 15;
    const int ty = tid >> 4;
    const int m0 = blockIdx.x * 128;

    const int lrow = tid >> 1;
    const int lk   = (tid & 1) * 4;

    const float* Ag = A + (size_t)(m0 + lrow) * K + lk;
    const float* Wg = W + (size_t)lrow * K + lk;   // N = 128 rows exactly

    float acc[8][8];
    #pragma unroll
    for (int i = 0; i < 8; i++)
        #pragma unroll
        for (int j = 0; j < 8; j++) acc[i][j] = 0.f;

    float4 av = *(const float4*)(Ag);
    float4 wv = *(const float4*)(Wg);

    for (int k0 = 0; k0 < K; k0 += 8) {
        __syncthreads();
        As[lk+0][lrow] = av.x; As[lk+1][lrow] = av.y;
        As[lk+2][lrow] = av.z; As[lk+3][lrow] = av.w;
        Ws[lk+0][lrow] = wv.x; Ws[lk+1][lrow] = wv.y;
        Ws[lk+2][lrow] = wv.z; Ws[lk+3][lrow] = wv.w;
        __syncthreads();
        if (k0 + 8 < K) {
            av = *(const float4*)(Ag + k0 + 8);
            wv = *(const float4*)(Wg + k0 + 8);
        }
        #pragma unroll
        for (int kk = 0; kk < 8; kk++) {
            float a[8], b[8];
            float4 a0 = *(const float4*)&As[kk][ty * 8];
            float4 a1 = *(const float4*)&As[kk][ty * 8 + 4];
            float4 b0 = *(const float4*)&Ws[kk][tx * 8];
            float4 b1 = *(const float4*)&Ws[kk][tx * 8 + 4];
            a[0]=a0.x; a[1]=a0.y; a[2]=a0.z; a[3]=a0.w;
            a[4]=a1.x; a[5]=a1.y; a[6]=a1.z; a[7]=a1.w;
            b[0]=b0.x; b[1]=b0.y; b[2]=b0.z; b[3]=b0.w;
            b[4]=b1.x; b[5]=b1.y; b[6]=b1.z; b[7]=b1.w;
            #pragma unroll
            for (int i = 0; i < 8; i++)
                #pragma unroll
                for (int j = 0; j < 8; j++)
                    acc[i][j] += a[i] * b[j];
        }
    }

    // epilogue: + bias + residual, LayerNorm per row, scale/shift, store
    float bv[8], gv[8], bb[8];
    {
        const int c = tx * 8;
        float4 t0 = *(const float4*)(bias + c);
        float4 t1 = *(const float4*)(bias + c + 4);
        bv[0]=t0.x; bv[1]=t0.y; bv[2]=t0.z; bv[3]=t0.w;
        bv[4]=t1.x; bv[5]=t1.y; bv[6]=t1.z; bv[7]=t1.w;
        t0 = *(const float4*)(lng + c); t1 = *(const float4*)(lng + c + 4);
        gv[0]=t0.x; gv[1]=t0.y; gv[2]=t0.z; gv[3]=t0.w;
        gv[4]=t1.x; gv[5]=t1.y; gv[6]=t1.z; gv[7]=t1.w;
        t0 = *(const float4*)(lnb + c); t1 = *(const float4*)(lnb + c + 4);
        bb[0]=t0.x; bb[1]=t0.y; bb[2]=t0.z; bb[3]=t0.w;
        bb[4]=t1.x; bb[5]=t1.y; bb[6]=t1.z; bb[7]=t1.w;
    }

    #pragma unroll
    for (int i = 0; i < 8; i++) {
        const int m = m0 + ty * 8 + i;
        const float* rp = res + (size_t)m * DD + tx * 8;
        float4 r0 = *(const float4*)(rp);
        float4 r1 = *(const float4*)(rp + 4);
        float v[8];
        v[0]=acc[i][0]+bv[0]+r0.x; v[1]=acc[i][1]+bv[1]+r0.y;
        v[2]=acc[i][2]+bv[2]+r0.z; v[3]=acc[i][3]+bv[3]+r0.w;
        v[4]=acc[i][4]+bv[4]+r1.x; v[5]=acc[i][5]+bv[5]+r1.y;
        v[6]=acc[i][6]+bv[6]+r1.z; v[7]=acc[i][7]+bv[7]+r1.w;

        float s = 0.f, s2 = 0.f;
        #pragma unroll
        for (int j = 0; j < 8; j++) { s += v[j]; s2 += v[j] * v[j]; }
        #pragma unroll
        for (int off = 1; off < 16; off <<= 1) {
            s  += __shfl_xor_sync(0xffffffffu, s,  off);
            s2 += __shfl_xor_sync(0xffffffffu, s2, off);
        }
        const float mu  = s * (1.f / DD);
        const float var = s2 * (1.f / DD) - mu * mu;
        const float r   = rsqrtf(var + 1e-5f);

        float o[8];
        #pragma unroll
        for (int j = 0; j < 8; j++) o[j] = (v[j] - mu) * r * gv[j] + bb[j];
        float* cp = C + (size_t)m * DD + tx * 8;
        *(float4*)(cp)     = make_float4(o[0], o[1], o[2], o[3]);
        *(float4*)(cp + 4) = make_float4(o[4], o[5], o[6], o[7]);
    }
}

// ---------------- temporal attention: seq = T=12 over (b, n), per head -----
__global__ __launch_bounds__(256) void temporal_attn_kernel(
    const float* __restrict__ qkv, float* __restrict__ out)
{
    __shared__ float s[TT][D3];   // 18 KB
    const int bn = blockIdx.x;
    const int b = bn / NS, n = bn % NS;

    for (int idx = threadIdx.x; idx < TT * D3; idx += 256) {
        const int t = idx / D3, c = idx % D3;
        s[t][c] = qkv[(size_t)((b * TT + t) * NS + n) * D3 + c];
    }
    __syncthreads();

    const int h = threadIdx.x >> 5;
    const int lane = threadIdx.x & 31;
    if (lane < TT) {
        const int tq = lane;
        float q[HD];
        #pragma unroll
        for (int d = 0; d < HD; d++) q[d] = s[tq][h * HD + d];

        float sc[TT];
        float mx = -1e30f;
        #pragma unroll
        for (int tk = 0; tk < TT; tk++) {
            float a = 0.f;
            #pragma unroll
            for (int d = 0; d < HD; d++) a += q[d] * s[tk][DD + h * HD + d];
            a *= 0.25f;           // 1/sqrt(16)
            sc[tk] = a;
            mx = fmaxf(mx, a);
        }
        float sum = 0.f;
        #pragma unroll
        for (int tk = 0; tk < TT; tk++) { sc[tk] = __expf(sc[tk] - mx); sum += sc[tk]; }
        const float inv = 1.f / sum;

        float o[HD];
        #pragma unroll
        for (int d = 0; d < HD; d++) o[d] = 0.f;
        #pragma unroll
        for (int tk = 0; tk < TT; tk++) {
            const float p = sc[tk] * inv;
            #pragma unroll
            for (int d = 0; d < HD; d++) o[d] += p * s[tk][2 * DD + h * HD + d];
        }
        const size_t ob = (size_t)((b * TT + tq) * NS + n) * DD + h * HD;
        #pragma unroll
        for (int d = 0; d < HD; d += 4)
            *(float4*)(out + ob + d) = make_float4(o[d], o[d+1], o[d+2], o[d+3]);
    }
}

// ---------------- spatial attention: seq = N=325 over (b,t), + graph bias --
#define NCHUNK 11   // ceil(325/32)
__global__ __launch_bounds__(256) void spatial_attn_kernel(
    const float* __restrict__ qkv, const float* __restrict__ bias,
    float* __restrict__ out)
{
    __shared__ float ks[NS * 17];
    __shared__ float vs[NS * 17];
    const int bt = blockIdx.x;
    const int h  = blockIdx.y;
    const int m0 = bt * NS;

    for (int idx = threadIdx.x; idx < NS * HD; idx += 256) {
        const int j = idx >> 4, d = idx & 15;
        const float* row = qkv + (size_t)(m0 + j) * D3;
        ks[j * 17 + d] = row[DD     + h * HD + d];
        vs[j * 17 + d] = row[2 * DD + h * HD + d];
    }
    __syncthreads();

    const int warp = threadIdx.x >> 5;
    const int lane = threadIdx.x & 31;

    for (int nq = warp; nq < NS; nq += 8) {
        float q[HD];
        const float* qrow = qkv + (size_t)(m0 + nq) * D3 + h * HD;
        #pragma unroll
        for (int d = 0; d < HD; d++) q[d] = qrow[d];

        float sl[NCHUNK];
        float mx = -1e30f;
        #pragma unroll
        for (int c = 0; c < NCHUNK; c++) {
            const int j = lane + c * 32;
            if (j < NS) {
                float a = 0.f;
                #pragma unroll
                for (int d = 0; d < HD; d++) a += q[d] * ks[j * 17 + d];
                a = a * 0.25f + bias[nq * NS + j];
                sl[c] = a;
                mx = fmaxf(mx, a);
            } else sl[c] = -1e30f;
        }
        #pragma unroll
        for (int off = 16; off > 0; off >>= 1)
            mx = fmaxf(mx, __shfl_xor_sync(0xffffffffu, mx, off));

        float sum = 0.f;
        #pragma unroll
        for (int c = 0; c < NCHUNK; c++) {
            const int j = lane + c * 32;
            float e = (j < NS) ? __expf(sl[c] - mx) : 0.f;
            sl[c] = e;
            sum += e;
        }
        #pragma unroll
        for (int off = 16; off > 0; off >>= 1)
            sum += __shfl_xor_sync(0xffffffffu, sum, off);
        const float inv = 1.f / sum;

        float o[HD];
        #pragma unroll
        for (int d = 0; d < HD; d++) o[d] = 0.f;
        #pragma unroll
        for (int c = 0; c < NCHUNK; c++) {
            const int j = lane + c * 32;
            if (j < NS) {
                const float p = sl[c];
                #pragma unroll
                for (int d = 0; d < HD; d++) o[d] += p * vs[j * 17 + d];
            }
        }
        #pragma unroll
        for (int d = 0; d < HD; d++) {
            #pragma unroll
            for (int off = 16; off > 0; off >>= 1)
                o[d] += __shfl_xor_sync(0xffffffffu, o[d], off);
        }
        if (lane == 0) {
            const size_t ob = (size_t)(m0 + nq) * DD + h * HD;
            #pragma unroll
            for (int d = 0; d < HD; d += 4)
                *(float4*)(out + ob + d) =
                    make_float4(o[d]*inv, o[d+1]*inv, o[d+2]*inv, o[d+3]*inv);
        }
    }
}

// ---------------- launch ---------------------------------------------------
extern "C" void kernel_launch(void* const* d_in, const int* in_sizes, int n_in,
                              void* d_out, int out_size)
{
    const float* x       = (const float*)d_in[0];
    const float* t_w_in  = (const float*)d_in[1];
    const float* t_b_in  = (const float*)d_in[2];
    const float* t_w_out = (const float*)d_in[3];
    const float* t_b_out = (const float*)d_in[4];
    const float* s_w_in  = (const float*)d_in[5];
    const float* s_b_in  = (const float*)d_in[6];
    const float* s_w_out = (const float*)d_in[7];
    const float* s_b_out = (const float*)d_in[8];
    const float* gbias   = (const float*)d_in[9];
    const float* nt_g    = (const float*)d_in[10];
    const float* nt_b    = (const float*)d_in[11];
    const float* ns_g    = (const float*)d_in[12];
    const float* ns_b    = (const float*)d_in[13];
    const float* ff_w1   = (const float*)d_in[14];
    const float* ff_b1   = (const float*)d_in[15];
    const float* ff_w2   = (const float*)d_in[16];
    const float* ff_b2   = (const float*)d_in[17];
    const float* nf_g    = (const float*)d_in[18];
    const float* nf_b    = (const float*)d_in[19];
    float* out = (float*)d_out;

    float *qkv, *attn, *x1, *x2, *hid;
    cudaGetSymbolAddress((void**)&qkv,  g_qkv);
    cudaGetSymbolAddress((void**)&attn, g_attn);
    cudaGetSymbolAddress((void**)&x1,   g_x1);
    cudaGetSymbolAddress((void**)&x2,   g_x2);
    cudaGetSymbolAddress((void**)&hid,  g_hid);

    const int M = MTOK;          // 124800 = 975 * 128
    const dim3 blk(256);

    // 1) temporal QKV projection  [M,128] @ [384,128]^T
    gemm_nt_kernel<0><<<dim3(D3/128, M/128), blk>>>(x, t_w_in, t_b_in, qkv, M, D3, DD);
    // 2) temporal attention
    temporal_attn_kernel<<<BB * NS, blk>>>(qkv, attn);
    // 3) temporal out-proj + residual(x) + LN  -> x1
    gemm_nt_ln_kernel<<<M/128, blk>>>(attn, t_w_out, t_b_out, x, nt_g, nt_b, x1, M, DD);
    // 4) spatial QKV projection
    gemm_nt_kernel<0><<<dim3(D3/128, M/128), blk>>>(x1, s_w_in, s_b_in, qkv, M, D3, DD);
    // 5) spatial attention with graph bias
    spatial_attn_kernel<<<dim3(BB*TT, HH), blk>>>(qkv, gbias, attn);
    // 6) spatial out-proj + residual(x1) + LN -> x2
    gemm_nt_ln_kernel<<<M/128, blk>>>(attn, s_w_out, s_b_out, x1, ns_g, ns_b, x2, M, DD);
    // 7) FFN up + GELU  [M,128] @ [512,128]^T
    gemm_nt_kernel<1><<<dim3(FF/128, M/128), blk>>>(x2, ff_w1, ff_b1, hid, M, FF, DD);
    // 8) FFN down + residual(x2) + LN -> output
    gemm_nt_ln_kernel<<<M/128, blk>>>(hid, ff_w2, ff_b2, x2, nf_g, nf_b, out, M, FF);
}

// round 4
// speedup vs baseline: 1.1926x; 1.1926x over previous
#include <cuda_runtime.h>
#include <math.h>

// Problem dims (fixed by reference setup_inputs)
#define BB 32
#define TT 12
#define NS 325          // sensors
#define DD 128
#define HH 8
#define HD 16
#define FF 512
#define D3 384
#define MTOK (BB*TT*NS) // 124800 tokens

typedef unsigned long long ull;

// ---------------- f32x2 packed-FMA helpers (Blackwell FFMA2) ---------------
__device__ __forceinline__ ull splat2(float x) {
    ull r; asm("mov.b64 %0, {%1, %1};" : "=l"(r) : "f"(x)); return r;
}
__device__ __forceinline__ ull pack2(float x, float y) {
    ull r; asm("mov.b64 %0, {%1, %2};" : "=l"(r) : "f"(x), "f"(y)); return r;
}
__device__ __forceinline__ void ffma2(ull& d, ull a, ull b) {
    asm("fma.rn.f32x2 %0, %1, %2, %3;" : "=l"(d) : "l"(a), "l"(b), "l"(d));
}
__device__ __forceinline__ float2 unpack2(ull r) {
    float x, y; asm("mov.b64 {%0, %1}, %2;" : "=f"(x), "=f"(y) : "l"(r));
    return make_float2(x, y);
}

// ---------------- scratch (device globals; no allocation allowed) ----------
__device__ float g_qkv [(size_t)MTOK * D3];
__device__ float g_attn[(size_t)MTOK * DD];
__device__ float g_x1  [(size_t)MTOK * DD];
__device__ float g_x2  [(size_t)MTOK * DD];
__device__ float g_hid [(size_t)MTOK * FF];

__device__ __forceinline__ float gelu_f(float v) {
    // tanh-approx GELU via sigmoid identity: 0.5v(1+tanh(u)) = v*sigmoid(2u)
    const float u2 = 1.5957691216057308f * (v + 0.044715f * v * v * v);
    return v * (1.0f / (1.0f + __expf(-u2)));
}

// ---------------- NT SGEMM: C[M,N] = A[M,K] @ W[N,K]^T + bias --------------
// BM=BN=128, BK=8, 256 threads. Warps 2(m)x4(n) over 64x32 warp tiles;
// lanes 8(m)x4(n), 8x8 microtile, accumulators paired over n via FFMA2.
// EPI: 0 = bias only, 1 = bias + GELU
template<int EPI>
__global__ __launch_bounds__(256, 2) void gemm_nt_kernel(
    const float* __restrict__ A, const float* __restrict__ W,
    const float* __restrict__ bias, float* __restrict__ C,
    int M, int N, int K)
{
    __shared__ float As[8][132];
    __shared__ float Ws[8][132];
    const int tid  = threadIdx.x;
    const int warp = tid >> 5, lane = tid & 31;
    const int wm = warp >> 2, wn = warp & 3;     // 2 x 4 warps
    const int lm = lane & 7,  ln = lane >> 3;    // 8 x 4 lanes
    const int row_a = wm * 64 + lm * 8;          // tile-local row base
    const int col_b = wn * 32 + ln * 8;          // tile-local col base
    const int m0 = blockIdx.y * 128;
    const int n0 = blockIdx.x * 128;

    const int lrow = tid >> 1;        // 0..127
    const int lk   = (tid & 1) * 4;   // 0 or 4

    const float* Ag = A + (size_t)(m0 + lrow) * K + lk;
    const float* Wg = W + (size_t)(n0 + lrow) * K + lk;

    ull acc2[8][4];
    #pragma unroll
    for (int i = 0; i < 8; i++)
        #pragma unroll
        for (int j = 0; j < 4; j++) acc2[i][j] = 0ull;

    float4 av = *(const float4*)(Ag);
    float4 wv = *(const float4*)(Wg);

    for (int k0 = 0; k0 < K; k0 += 8) {
        __syncthreads();
        As[lk+0][lrow] = av.x; As[lk+1][lrow] = av.y;
        As[lk+2][lrow] = av.z; As[lk+3][lrow] = av.w;
        Ws[lk+0][lrow] = wv.x; Ws[lk+1][lrow] = wv.y;
        Ws[lk+2][lrow] = wv.z; Ws[lk+3][lrow] = wv.w;
        __syncthreads();
        if (k0 + 8 < K) {
            av = *(const float4*)(Ag + k0 + 8);
            wv = *(const float4*)(Wg + k0 + 8);
        }
        #pragma unroll
        for (int kk = 0; kk < 8; kk++) {
            float4 a0 = *(const float4*)&As[kk][row_a];
            float4 a1 = *(const float4*)&As[kk][row_a + 4];
            ulonglong2 b01 = *(const ulonglong2*)&Ws[kk][col_b];
            ulonglong2 b23 = *(const ulonglong2*)&Ws[kk][col_b + 4];
            ull aa[8];
            aa[0]=splat2(a0.x); aa[1]=splat2(a0.y); aa[2]=splat2(a0.z); aa[3]=splat2(a0.w);
            aa[4]=splat2(a1.x); aa[5]=splat2(a1.y); aa[6]=splat2(a1.z); aa[7]=splat2(a1.w);
            ull bb[4] = {b01.x, b01.y, b23.x, b23.y};
            #pragma unroll
            for (int i = 0; i < 8; i++)
                #pragma unroll
                for (int j = 0; j < 4; j++)
                    ffma2(acc2[i][j], aa[i], bb[j]);
        }
    }

    float bv[8];
    #pragma unroll
    for (int j = 0; j < 8; j++) bv[j] = bias[n0 + col_b + j];

    #pragma unroll
    for (int i = 0; i < 8; i++) {
        const int m = m0 + row_a + i;
        float o[8];
        #pragma unroll
        for (int jp = 0; jp < 4; jp++) {
            float2 f = unpack2(acc2[i][jp]);
            o[2*jp]   = f.x + bv[2*jp];
            o[2*jp+1] = f.y + bv[2*jp+1];
        }
        if (EPI == 1) {
            #pragma unroll
            for (int j = 0; j < 8; j++) o[j] = gelu_f(o[j]);
        }
        float* cp = C + (size_t)m * N + n0 + col_b;
        *(float4*)(cp)     = make_float4(o[0], o[1], o[2], o[3]);
        *(float4*)(cp + 4) = make_float4(o[4], o[5], o[6], o[7]);
    }
}

// ------- NT SGEMM fused with residual + LayerNorm. N fixed at 128. --------
// out = LN(res + A@W^T + bias) * g + b. Cross-warp LN reduce via smem.
__global__ __launch_bounds__(256, 2) void gemm_nt_ln_kernel(
    const float* __restrict__ A, const float* __restrict__ W,
    const float* __restrict__ bias, const float* __restrict__ res,
    const float* __restrict__ lng, const float* __restrict__ lnb,
    float* __restrict__ C, int M, int K)
{
    __shared__ float As[8][132];
    __shared__ float Ws[8][132];
    __shared__ float2 wred[128][4];   // per-row (sum, sumsq) partials by wn
    const int tid  = threadIdx.x;
    const int warp = tid >> 5, lane = tid & 31;
    const int wm = warp >> 2, wn = warp & 3;
    const int lm = lane & 7,  ln = lane >> 3;
    const int row_a = wm * 64 + lm * 8;
    const int col_b = wn * 32 + ln * 8;
    const int m0 = blockIdx.x * 128;

    const int lrow = tid >> 1;
    const int lk   = (tid & 1) * 4;

    const float* Ag = A + (size_t)(m0 + lrow) * K + lk;
    const float* Wg = W + (size_t)lrow * K + lk;   // N = 128 rows exactly

    ull acc2[8][4];
    #pragma unroll
    for (int i = 0; i < 8; i++)
        #pragma unroll
        for (int j = 0; j < 4; j++) acc2[i][j] = 0ull;

    float4 av = *(const float4*)(Ag);
    float4 wv = *(const float4*)(Wg);

    for (int k0 = 0; k0 < K; k0 += 8) {
        __syncthreads();
        As[lk+0][lrow] = av.x; As[lk+1][lrow] = av.y;
        As[lk+2][lrow] = av.z; As[lk+3][lrow] = av.w;
        Ws[lk+0][lrow] = wv.x; Ws[lk+1][lrow] = wv.y;
        Ws[lk+2][lrow] = wv.z; Ws[lk+3][lrow] = wv.w;
        __syncthreads();
        if (k0 + 8 < K) {
            av = *(const float4*)(Ag + k0 + 8);
            wv = *(const float4*)(Wg + k0 + 8);
        }
        #pragma unroll
        for (int kk = 0; kk < 8; kk++) {
            float4 a0 = *(const float4*)&As[kk][row_a];
            float4 a1 = *(const float4*)&As[kk][row_a + 4];
            ulonglong2 b01 = *(const ulonglong2*)&Ws[kk][col_b];
            ulonglong2 b23 = *(const ulonglong2*)&Ws[kk][col_b + 4];
            ull aa[8];
            aa[0]=splat2(a0.x); aa[1]=splat2(a0.y); aa[2]=splat2(a0.z); aa[3]=splat2(a0.w);
            aa[4]=splat2(a1.x); aa[5]=splat2(a1.y); aa[6]=splat2(a1.z); aa[7]=splat2(a1.w);
            ull bb[4] = {b01.x, b01.y, b23.x, b23.y};
            #pragma unroll
            for (int i = 0; i < 8; i++)
                #pragma unroll
                for (int j = 0; j < 4; j++)
                    ffma2(acc2[i][j], aa[i], bb[j]);
        }
    }

    float bv[8];
    #pragma unroll
    for (int j = 0; j < 8; j++) bv[j] = bias[col_b + j];

    // pass 1: row partial sums -> warp reduce across ln -> smem by wn
    #pragma unroll
    for (int i = 0; i < 8; i++) {
        const int m = m0 + row_a + i;
        const float* rp = res + (size_t)m * DD + col_b;
        float4 r0 = *(const float4*)(rp);
        float4 r1 = *(const float4*)(rp + 4);
        float v[8];
        float2 f;
        f = unpack2(acc2[i][0]); v[0]=f.x+bv[0]+r0.x; v[1]=f.y+bv[1]+r0.y;
        f = unpack2(acc2[i][1]); v[2]=f.x+bv[2]+r0.z; v[3]=f.y+bv[3]+r0.w;
        f = unpack2(acc2[i][2]); v[4]=f.x+bv[4]+r1.x; v[5]=f.y+bv[5]+r1.y;
        f = unpack2(acc2[i][3]); v[6]=f.x+bv[6]+r1.z; v[7]=f.y+bv[7]+r1.w;
        float s = 0.f, s2 = 0.f;
        #pragma unroll
        for (int j = 0; j < 8; j++) { s += v[j]; s2 += v[j]*v[j]; }
        s  += __shfl_xor_sync(0xffffffffu, s,  8);
        s2 += __shfl_xor_sync(0xffffffffu, s2, 8);
        s  += __shfl_xor_sync(0xffffffffu, s,  16);
        s2 += __shfl_xor_sync(0xffffffffu, s2, 16);
        if (lane < 8) wred[row_a + i][wn] = make_float2(s, s2);
    }
    __syncthreads();

    float gv[8], bb2[8];
    #pragma unroll
    for (int j = 0; j < 8; j++) {
        gv[j]  = lng[col_b + j];
        bb2[j] = lnb[col_b + j];
    }

    // pass 2: finalize
    #pragma unroll
    for (int i = 0; i < 8; i++) {
        const int m = m0 + row_a + i;
        float2 p0 = wred[row_a + i][0];
        float2 p1 = wred[row_a + i][1];
        float2 p2 = wred[row_a + i][2];
        float2 p3 = wred[row_a + i][3];
        const float s  = p0.x + p1.x + p2.x + p3.x;
        const float s2 = p0.y + p1.y + p2.y + p3.y;
        const float mu  = s * (1.f / DD);
        const float var = s2 * (1.f / DD) - mu * mu;
        const float rstd = rsqrtf(var + 1e-5f);

        const float* rp = res + (size_t)m * DD + col_b;
        float4 r0 = *(const float4*)(rp);
        float4 r1 = *(const float4*)(rp + 4);
        float v[8];
        float2 f;
        f = unpack2(acc2[i][0]); v[0]=f.x+bv[0]+r0.x; v[1]=f.y+bv[1]+r0.y;
        f = unpack2(acc2[i][1]); v[2]=f.x+bv[2]+r0.z; v[3]=f.y+bv[3]+r0.w;
        f = unpack2(acc2[i][2]); v[4]=f.x+bv[4]+r1.x; v[5]=f.y+bv[5]+r1.y;
        f = unpack2(acc2[i][3]); v[6]=f.x+bv[6]+r1.z; v[7]=f.y+bv[7]+r1.w;

        float o[8];
        #pragma unroll
        for (int j = 0; j < 8; j++) o[j] = (v[j] - mu) * rstd * gv[j] + bb2[j];
        float* cp = C + (size_t)m * DD + col_b;
        *(float4*)(cp)     = make_float4(o[0], o[1], o[2], o[3]);
        *(float4*)(cp + 4) = make_float4(o[4], o[5], o[6], o[7]);
    }
}

// ---------------- temporal attention: seq = T=12 over (b, n), per head -----
__global__ __launch_bounds__(256) void temporal_attn_kernel(
    const float* __restrict__ qkv, float* __restrict__ out)
{
    __shared__ float s[TT][D3];   // 18 KB
    const int bn = blockIdx.x;
    const int b = bn / NS, n = bn % NS;

    for (int idx = threadIdx.x; idx < TT * D3; idx += 256) {
        const int t = idx / D3, c = idx % D3;
        s[t][c] = qkv[(size_t)((b * TT + t) * NS + n) * D3 + c];
    }
    __syncthreads();

    const int h = threadIdx.x >> 5;
    const int lane = threadIdx.x & 31;
    if (lane < TT) {
        const int tq = lane;
        float q[HD];
        #pragma unroll
        for (int d = 0; d < HD; d++) q[d] = s[tq][h * HD + d];

        float sc[TT];
        float mx = -1e30f;
        #pragma unroll
        for (int tk = 0; tk < TT; tk++) {
            float a = 0.f;
            #pragma unroll
            for (int d = 0; d < HD; d++) a += q[d] * s[tk][DD + h * HD + d];
            a *= 0.25f;           // 1/sqrt(16)
            sc[tk] = a;
            mx = fmaxf(mx, a);
        }
        float sum = 0.f;
        #pragma unroll
        for (int tk = 0; tk < TT; tk++) { sc[tk] = __expf(sc[tk] - mx); sum += sc[tk]; }
        const float inv = 1.f / sum;

        float o[HD];
        #pragma unroll
        for (int d = 0; d < HD; d++) o[d] = 0.f;
        #pragma unroll
        for (int tk = 0; tk < TT; tk++) {
            const float p = sc[tk] * inv;
            #pragma unroll
            for (int d = 0; d < HD; d++) o[d] += p * s[tk][2 * DD + h * HD + d];
        }
        const size_t ob = (size_t)((b * TT + tq) * NS + n) * DD + h * HD;
        #pragma unroll
        for (int d = 0; d < HD; d += 4)
            *(float4*)(out + ob + d) = make_float4(o[d], o[d+1], o[d+2], o[d+3]);
    }
}

// ---------------- spatial attention v2: lane-owns-query, no shuffles -------
// grid (B*T, H), 352 threads (11 warps >= 325 queries). K/V staged in smem
// (broadcast reads), bias staged per-32-key tile with coalesced loads.
// Single pass with unnormalized exp (scores bounded, no max needed).
#define SPT 352
__global__ __launch_bounds__(SPT, 2) void spatial_attn_kernel(
    const float* __restrict__ qkv, const float* __restrict__ bias,
    float* __restrict__ out)
{
    extern __shared__ float sm[];
    float* ks = sm;                    // [NS*16]
    float* vs = sm + NS * HD;          // [NS*16]
    float* sb = sm + 2 * NS * HD;      // [NS][33] bias tile (padded)
    const int bt = blockIdx.x;
    const int h  = blockIdx.y;
    const int m0 = bt * NS;
    const int tid = threadIdx.x;

    for (int idx = tid; idx < NS * HD; idx += SPT) {
        const int j = idx >> 4, d = idx & 15;
        const float* row = qkv + (size_t)(m0 + j) * D3 + h * HD + d;
        ks[j * 16 + d] = row[DD];
        vs[j * 16 + d] = row[2 * DD];
    }

    const int q = tid;
    ull q2[8];
    if (q < NS) {
        const float* qr = qkv + (size_t)(m0 + q) * D3 + h * HD;
        #pragma unroll
        for (int p = 0; p < 8; p++) q2[p] = pack2(qr[2*p], qr[2*p+1]);
    }
    ull o2[8];
    #pragma unroll
    for (int p = 0; p < 8; p++) o2[p] = 0ull;
    float lsum = 0.f;

    for (int jt = 0; jt < NS; jt += 32) {
        __syncthreads();
        for (int idx = tid; idx < NS * 32; idx += SPT) {
            const int r = idx >> 5, c = idx & 31;
            const int jj = jt + c;
            sb[r * 33 + c] = (jj < NS) ? bias[r * NS + jj] : 0.f;
        }
        __syncthreads();
        if (q < NS) {
            const int jmax = (NS - jt < 32) ? (NS - jt) : 32;
            for (int jl = 0; jl < jmax; jl++) {
                const int j = jt + jl;
                const ulonglong2* kp = (const ulonglong2*)(ks + j * 16);
                ulonglong2 k01 = kp[0], k23 = kp[1];
                ull acc = 0ull;
                ffma2(acc, q2[0], k01.x); ffma2(acc, q2[1], k01.y);
                ffma2(acc, q2[2], k23.x); ffma2(acc, q2[3], k23.y);
                ulonglong2 k45 = kp[2], k67 = kp[3];
                ffma2(acc, q2[4], k45.x); ffma2(acc, q2[5], k45.y);
                ffma2(acc, q2[6], k67.x); ffma2(acc, q2[7], k67.y);
                float2 sp = unpack2(acc);
                const float s = (sp.x + sp.y) * 0.25f + sb[q * 33 + jl];
                const float e = __expf(s);
                lsum += e;
                const ull ee = splat2(e);
                const ulonglong2* vp = (const ulonglong2*)(vs + j * 16);
                ulonglong2 v01 = vp[0], v23 = vp[1];
                ffma2(o2[0], ee, v01.x); ffma2(o2[1], ee, v01.y);
                ffma2(o2[2], ee, v23.x); ffma2(o2[3], ee, v23.y);
                ulonglong2 v45 = vp[2], v67 = vp[3];
                ffma2(o2[4], ee, v45.x); ffma2(o2[5], ee, v45.y);
                ffma2(o2[6], ee, v67.x); ffma2(o2[7], ee, v67.y);
            }
        }
    }

    if (q < NS) {
        const float inv = 1.f / lsum;
        float o[16];
        #pragma unroll
        for (int p = 0; p < 8; p++) {
            float2 f = unpack2(o2[p]);
            o[2*p]   = f.x * inv;
            o[2*p+1] = f.y * inv;
        }
        float* op = out + (size_t)(m0 + q) * DD + h * HD;
        #pragma unroll
        for (int d = 0; d < 16; d += 4)
            *(float4*)(op + d) = make_float4(o[d], o[d+1], o[d+2], o[d+3]);
    }
}

#define SP_SMEM (2 * NS * HD * 4 + NS * 33 * 4)   // 41600 + 42900 = 84500 B

// ---------------- launch ---------------------------------------------------
extern "C" void kernel_launch(void* const* d_in, const int* in_sizes, int n_in,
                              void* d_out, int out_size)
{
    const float* x       = (const float*)d_in[0];
    const float* t_w_in  = (const float*)d_in[1];
    const float* t_b_in  = (const float*)d_in[2];
    const float* t_w_out = (const float*)d_in[3];
    const float* t_b_out = (const float*)d_in[4];
    const float* s_w_in  = (const float*)d_in[5];
    const float* s_b_in  = (const float*)d_in[6];
    const float* s_w_out = (const float*)d_in[7];
    const float* s_b_out = (const float*)d_in[8];
    const float* gbias   = (const float*)d_in[9];
    const float* nt_g    = (const float*)d_in[10];
    const float* nt_b    = (const float*)d_in[11];
    const float* ns_g    = (const float*)d_in[12];
    const float* ns_b    = (const float*)d_in[13];
    const float* ff_w1   = (const float*)d_in[14];
    const float* ff_b1   = (const float*)d_in[15];
    const float* ff_w2   = (const float*)d_in[16];
    const float* ff_b2   = (const float*)d_in[17];
    const float* nf_g    = (const float*)d_in[18];
    const float* nf_b    = (const float*)d_in[19];
    float* out = (float*)d_out;

    float *qkv, *attn, *x1, *x2, *hid;
    cudaGetSymbolAddress((void**)&qkv,  g_qkv);
    cudaGetSymbolAddress((void**)&attn, g_attn);
    cudaGetSymbolAddress((void**)&x1,   g_x1);
    cudaGetSymbolAddress((void**)&x2,   g_x2);
    cudaGetSymbolAddress((void**)&hid,  g_hid);

    cudaFuncSetAttribute(spatial_attn_kernel,
                         cudaFuncAttributeMaxDynamicSharedMemorySize, SP_SMEM);

    const int M = MTOK;          // 124800 = 975 * 128
    const dim3 blk(256);

    // 1) temporal QKV projection  [M,128] @ [384,128]^T
    gemm_nt_kernel<0><<<dim3(D3/128, M/128), blk>>>(x, t_w_in, t_b_in, qkv, M, D3, DD);
    // 2) temporal attention
    temporal_attn_kernel<<<BB * NS, blk>>>(qkv, attn);
    // 3) temporal out-proj + residual(x) + LN  -> x1
    gemm_nt_ln_kernel<<<M/128, blk>>>(attn, t_w_out, t_b_out, x, nt_g, nt_b, x1, M, DD);
    // 4) spatial QKV projection
    gemm_nt_kernel<0><<<dim3(D3/128, M/128), blk>>>(x1, s_w_in, s_b_in, qkv, M, D3, DD);
    // 5) spatial attention with graph bias
    spatial_attn_kernel<<<dim3(BB*TT, HH), SPT, SP_SMEM>>>(qkv, gbias, attn);
    // 6) spatial out-proj + residual(x1) + LN -> x2
    gemm_nt_ln_kernel<<<M/128, blk>>>(attn, s_w_out, s_b_out, x1, ns_g, ns_b, x2, M, DD);
    // 7) FFN up + GELU  [M,128] @ [512,128]^T
    gemm_nt_kernel<1><<<dim3(FF/128, M/128), blk>>>(x2, ff_w1, ff_b1, hid, M, FF, DD);
    // 8) FFN down + residual(x2) + LN -> output
    gemm_nt_ln_kernel<<<M/128, blk>>>(hid, ff_w2, ff_b2, x2, nf_g, nf_b, out, M, FF);
}

// round 6
// speedup vs baseline: 1.3055x; 1.0946x over previous
#include <cuda_runtime.h>
#include <math.h>

// Problem dims (fixed by reference setup_inputs)
#define BB 32
#define TT 12
#define NS 325          // sensors
#define DD 128
#define HH 8
#define HD 16
#define FF 512
#define D3 384
#define MTOK (BB*TT*NS) // 124800 tokens

typedef unsigned long long ull;

// ---------------- f32x2 packed-FMA helpers (Blackwell FFMA2) ---------------
__device__ __forceinline__ ull splat2(float x) {
    ull r; asm("mov.b64 %0, {%1, %1};" : "=l"(r) : "f"(x)); return r;
}
__device__ __forceinline__ ull pack2(float x, float y) {
    ull r; asm("mov.b64 %0, {%1, %2};" : "=l"(r) : "f"(x), "f"(y)); return r;
}
__device__ __forceinline__ void ffma2(ull& d, ull a, ull b) {
    asm("fma.rn.f32x2 %0, %1, %2, %3;" : "=l"(d) : "l"(a), "l"(b), "l"(d));
}
__device__ __forceinline__ float2 unpack2(ull r) {
    float x, y; asm("mov.b64 {%0, %1}, %2;" : "=f"(x), "=f"(y) : "l"(r));
    return make_float2(x, y);
}

// ---------------- scratch (device globals; no allocation allowed) ----------
__device__ float g_qkv [(size_t)MTOK * D3];
__device__ float g_attn[(size_t)MTOK * DD];
__device__ float g_x1  [(size_t)MTOK * DD];
__device__ float g_x2  [(size_t)MTOK * DD];
__device__ float g_hid [(size_t)MTOK * FF];

__device__ __forceinline__ float gelu_f(float v) {
    // tanh-approx GELU via sigmoid identity: 0.5v(1+tanh(u)) = v*sigmoid(2u)
    const float u2 = 1.5957691216057308f * (v + 0.044715f * v * v * v);
    return v * (1.0f / (1.0f + __expf(-u2)));
}

// =============== NT SGEMM v3: C[M,N] = A[M,K] @ W[N,K]^T + bias ============
// 128 threads, block 128x128, BK=8. Warps 2x2 (64x64 tiles), lanes 8(m)x4(n).
// Microtile 8m x 16n: m-rows {lm*4+0..3, lm*4+32..35}, n-cols ln*16..+15.
// 6 LDS.128 per warp-kk vs 64 FFMA2 -> FFMA2-pipe bound.
// EPI: 0 = bias only, 1 = bias + GELU
template<int EPI>
__global__ __launch_bounds__(128, 2) void gemm_nt_kernel(
    const float* __restrict__ A, const float* __restrict__ W,
    const float* __restrict__ bias, float* __restrict__ C,
    int M, int N, int K)
{
    __shared__ float As[8][132];
    __shared__ float Ws[8][132];
    const int tid  = threadIdx.x;
    const int warp = tid >> 5, lane = tid & 31;
    const int wm = warp >> 1, wn = warp & 1;     // 2 x 2 warps
    const int lm = lane & 7,  ln = lane >> 3;    // 8 x 4 lanes
    const int ma0 = wm * 64 + lm * 4;            // rows ma0..+3
    const int ma1 = ma0 + 32;                    // rows ma1..+3
    const int nb  = wn * 64 + ln * 16;           // cols nb..+15
    const int m0 = blockIdx.y * 128;
    const int n0 = blockIdx.x * 128;

    const float* Ag = A + (size_t)(m0 + tid) * K;
    const float* Wg = W + (size_t)(n0 + tid) * K;

    ull acc2[8][8];
    #pragma unroll
    for (int i = 0; i < 8; i++)
        #pragma unroll
        for (int j = 0; j < 8; j++) acc2[i][j] = 0ull;

    float4 av0 = *(const float4*)(Ag);
    float4 av1 = *(const float4*)(Ag + 4);
    float4 wv0 = *(const float4*)(Wg);
    float4 wv1 = *(const float4*)(Wg + 4);

    for (int k0 = 0; k0 < K; k0 += 8) {
        __syncthreads();
        As[0][tid]=av0.x; As[1][tid]=av0.y; As[2][tid]=av0.z; As[3][tid]=av0.w;
        As[4][tid]=av1.x; As[5][tid]=av1.y; As[6][tid]=av1.z; As[7][tid]=av1.w;
        Ws[0][tid]=wv0.x; Ws[1][tid]=wv0.y; Ws[2][tid]=wv0.z; Ws[3][tid]=wv0.w;
        Ws[4][tid]=wv1.x; Ws[5][tid]=wv1.y; Ws[6][tid]=wv1.z; Ws[7][tid]=wv1.w;
        __syncthreads();
        if (k0 + 8 < K) {
            av0 = *(const float4*)(Ag + k0 + 8);
            av1 = *(const float4*)(Ag + k0 + 12);
            wv0 = *(const float4*)(Wg + k0 + 8);
            wv1 = *(const float4*)(Wg + k0 + 12);
        }
        #pragma unroll
        for (int kk = 0; kk < 8; kk++) {
            float4 a0 = *(const float4*)&As[kk][ma0];
            float4 a1 = *(const float4*)&As[kk][ma1];
            ulonglong2 b01 = *(const ulonglong2*)&Ws[kk][nb];
            ulonglong2 b23 = *(const ulonglong2*)&Ws[kk][nb + 4];
            ulonglong2 b45 = *(const ulonglong2*)&Ws[kk][nb + 8];
            ulonglong2 b67 = *(const ulonglong2*)&Ws[kk][nb + 12];
            ull aa[8];
            aa[0]=splat2(a0.x); aa[1]=splat2(a0.y); aa[2]=splat2(a0.z); aa[3]=splat2(a0.w);
            aa[4]=splat2(a1.x); aa[5]=splat2(a1.y); aa[6]=splat2(a1.z); aa[7]=splat2(a1.w);
            ull bb[8] = {b01.x, b01.y, b23.x, b23.y, b45.x, b45.y, b67.x, b67.y};
            #pragma unroll
            for (int i = 0; i < 8; i++)
                #pragma unroll
                for (int j = 0; j < 8; j++)
                    ffma2(acc2[i][j], aa[i], bb[j]);
        }
    }

    float bv[16];
    #pragma unroll
    for (int j = 0; j < 16; j += 4)
        *(float4*)&bv[j] = *(const float4*)(bias + n0 + nb + j);

    #pragma unroll
    for (int i = 0; i < 8; i++) {
        const int m = m0 + ((i < 4) ? (ma0 + i) : (ma1 + i - 4));
        float o[16];
        #pragma unroll
        for (int jp = 0; jp < 8; jp++) {
            float2 f = unpack2(acc2[i][jp]);
            o[2*jp]   = f.x + bv[2*jp];
            o[2*jp+1] = f.y + bv[2*jp+1];
        }
        if (EPI == 1) {
            #pragma unroll
            for (int j = 0; j < 16; j++) o[j] = gelu_f(o[j]);
        }
        float* cp = C + (size_t)m * N + n0 + nb;
        #pragma unroll
        for (int j = 0; j < 16; j += 4)
            *(float4*)(cp + j) = make_float4(o[j], o[j+1], o[j+2], o[j+3]);
    }
}

// ========= NT SGEMM v3 fused with residual + LayerNorm. N fixed 128 ========
// out = LN(res + A@W^T + bias) * g + b. Block covers full 128-col rows.
// Row reduce: shfl over ln (lanes +-8, +-16), then 2-warp smem partials.
__global__ __launch_bounds__(128, 2) void gemm_nt_ln_kernel(
    const float* __restrict__ A, const float* __restrict__ W,
    const float* __restrict__ bias, const float* __restrict__ res,
    const float* __restrict__ lng, const float* __restrict__ lnb,
    float* __restrict__ C, int M, int K)
{
    __shared__ float As[8][132];
    __shared__ float Ws[8][132];
    __shared__ float2 wred[128][2];
    const int tid  = threadIdx.x;
    const int warp = tid >> 5, lane = tid & 31;
    const int wm = warp >> 1, wn = warp & 1;
    const int lm = lane & 7,  ln = lane >> 3;
    const int ma0 = wm * 64 + lm * 4;
    const int ma1 = ma0 + 32;
    const int nb  = wn * 64 + ln * 16;
    const int m0 = blockIdx.x * 128;

    const float* Ag = A + (size_t)(m0 + tid) * K;
    const float* Wg = W + (size_t)tid * K;       // N = 128 rows exactly

    ull acc2[8][8];
    #pragma unroll
    for (int i = 0; i < 8; i++)
        #pragma unroll
        for (int j = 0; j < 8; j++) acc2[i][j] = 0ull;

    float4 av0 = *(const float4*)(Ag);
    float4 av1 = *(const float4*)(Ag + 4);
    float4 wv0 = *(const float4*)(Wg);
    float4 wv1 = *(const float4*)(Wg + 4);

    for (int k0 = 0; k0 < K; k0 += 8) {
        __syncthreads();
        As[0][tid]=av0.x; As[1][tid]=av0.y; As[2][tid]=av0.z; As[3][tid]=av0.w;
        As[4][tid]=av1.x; As[5][tid]=av1.y; As[6][tid]=av1.z; As[7][tid]=av1.w;
        Ws[0][tid]=wv0.x; Ws[1][tid]=wv0.y; Ws[2][tid]=wv0.z; Ws[3][tid]=wv0.w;
        Ws[4][tid]=wv1.x; Ws[5][tid]=wv1.y; Ws[6][tid]=wv1.z; Ws[7][tid]=wv1.w;
        __syncthreads();
        if (k0 + 8 < K) {
            av0 = *(const float4*)(Ag + k0 + 8);
            av1 = *(const float4*)(Ag + k0 + 12);
            wv0 = *(const float4*)(Wg + k0 + 8);
            wv1 = *(const float4*)(Wg + k0 + 12);
        }
        #pragma unroll
        for (int kk = 0; kk < 8; kk++) {
            float4 a0 = *(const float4*)&As[kk][ma0];
            float4 a1 = *(const float4*)&As[kk][ma1];
            ulonglong2 b01 = *(const ulonglong2*)&Ws[kk][nb];
            ulonglong2 b23 = *(const ulonglong2*)&Ws[kk][nb + 4];
            ulonglong2 b45 = *(const ulonglong2*)&Ws[kk][nb + 8];
            ulonglong2 b67 = *(const ulonglong2*)&Ws[kk][nb + 12];
            ull aa[8];
            aa[0]=splat2(a0.x); aa[1]=splat2(a0.y); aa[2]=splat2(a0.z); aa[3]=splat2(a0.w);
            aa[4]=splat2(a1.x); aa[5]=splat2(a1.y); aa[6]=splat2(a1.z); aa[7]=splat2(a1.w);
            ull bb[8] = {b01.x, b01.y, b23.x, b23.y, b45.x, b45.y, b67.x, b67.y};
            #pragma unroll
            for (int i = 0; i < 8; i++)
                #pragma unroll
                for (int j = 0; j < 8; j++)
                    ffma2(acc2[i][j], aa[i], bb[j]);
        }
    }

    float bv[16];
    #pragma unroll
    for (int j = 0; j < 16; j += 4)
        *(float4*)&bv[j] = *(const float4*)(bias + nb + j);

    // pass 1: v = acc + bias + residual; partial sums; reduce over ln + wn
    float vrow[8][16];
    #pragma unroll
    for (int i = 0; i < 8; i++) {
        const int m = m0 + ((i < 4) ? (ma0 + i) : (ma1 + i - 4));
        const float* rp = res + (size_t)m * DD + nb;
        #pragma unroll
        for (int j = 0; j < 16; j += 4) {
            float4 r = *(const float4*)(rp + j);
            float2 f0 = unpack2(acc2[i][j/2]);
            float2 f1 = unpack2(acc2[i][j/2 + 1]);
            vrow[i][j]   = f0.x + bv[j]   + r.x;
            vrow[i][j+1] = f0.y + bv[j+1] + r.y;
            vrow[i][j+2] = f1.x + bv[j+2] + r.z;
            vrow[i][j+3] = f1.y + bv[j+3] + r.w;
        }
        float s = 0.f, s2 = 0.f;
        #pragma unroll
        for (int j = 0; j < 16; j++) { s += vrow[i][j]; s2 += vrow[i][j]*vrow[i][j]; }
        s  += __shfl_xor_sync(0xffffffffu, s,  8);
        s2 += __shfl_xor_sync(0xffffffffu, s2, 8);
        s  += __shfl_xor_sync(0xffffffffu, s,  16);
        s2 += __shfl_xor_sync(0xffffffffu, s2, 16);
        if (ln == 0) {
            const int row = (i < 4) ? (ma0 + i) : (ma1 + i - 4);
            wred[row][wn] = make_float2(s, s2);
        }
    }
    __syncthreads();

    float gv[16], lb[16];
    #pragma unroll
    for (int j = 0; j < 16; j += 4) {
        *(float4*)&gv[j] = *(const float4*)(lng + nb + j);
        *(float4*)&lb[j] = *(const float4*)(lnb + nb + j);
    }

    #pragma unroll
    for (int i = 0; i < 8; i++) {
        const int row = (i < 4) ? (ma0 + i) : (ma1 + i - 4);
        const int m = m0 + row;
        float2 p0 = wred[row][0];
        float2 p1 = wred[row][1];
        const float s  = p0.x + p1.x;
        const float s2 = p0.y + p1.y;
        const float mu  = s * (1.f / DD);
        const float var = s2 * (1.f / DD) - mu * mu;
        const float rstd = rsqrtf(var + 1e-5f);
        float* cp = C + (size_t)m * DD + nb;
        #pragma unroll
        for (int j = 0; j < 16; j += 4) {
            float4 o;
            o.x = (vrow[i][j]   - mu) * rstd * gv[j]   + lb[j];
            o.y = (vrow[i][j+1] - mu) * rstd * gv[j+1] + lb[j+1];
            o.z = (vrow[i][j+2] - mu) * rstd * gv[j+2] + lb[j+2];
            o.w = (vrow[i][j+3] - mu) * rstd * gv[j+3] + lb[j+3];
            *(float4*)(cp + j) = o;
        }
    }
}

// ---------------- temporal attention: seq = T=12 over (b, n), per head -----
__global__ __launch_bounds__(256) void temporal_attn_kernel(
    const float* __restrict__ qkv, float* __restrict__ out)
{
    __shared__ float s[TT][D3];   // 18 KB
    const int bn = blockIdx.x;
    const int b = bn / NS, n = bn % NS;

    for (int idx = threadIdx.x; idx < TT * D3; idx += 256) {
        const int t = idx / D3, c = idx % D3;
        s[t][c] = qkv[(size_t)((b * TT + t) * NS + n) * D3 + c];
    }
    __syncthreads();

    const int h = threadIdx.x >> 5;
    const int lane = threadIdx.x & 31;
    if (lane < TT) {
        const int tq = lane;
        float q[HD];
        #pragma unroll
        for (int d = 0; d < HD; d++) q[d] = s[tq][h * HD + d];

        float sc[TT];
        float mx = -1e30f;
        #pragma unroll
        for (int tk = 0; tk < TT; tk++) {
            float a = 0.f;
            #pragma unroll
            for (int d = 0; d < HD; d++) a += q[d] * s[tk][DD + h * HD + d];
            a *= 0.25f;           // 1/sqrt(16)
            sc[tk] = a;
            mx = fmaxf(mx, a);
        }
        float sum = 0.f;
        #pragma unroll
        for (int tk = 0; tk < TT; tk++) { sc[tk] = __expf(sc[tk] - mx); sum += sc[tk]; }
        const float inv = 1.f / sum;

        float o[HD];
        #pragma unroll
        for (int d = 0; d < HD; d++) o[d] = 0.f;
        #pragma unroll
        for (int tk = 0; tk < TT; tk++) {
            const float p = sc[tk] * inv;
            #pragma unroll
            for (int d = 0; d < HD; d++) o[d] += p * s[tk][2 * DD + h * HD + d];
        }
        const size_t ob = (size_t)((b * TT + tq) * NS + n) * DD + h * HD;
        #pragma unroll
        for (int d = 0; d < HD; d += 4)
            *(float4*)(out + ob + d) = make_float4(o[d], o[d+1], o[d+2], o[d+3]);
    }
}

// ---------------- spatial attention v2: lane-owns-query, no shuffles -------
#define SPT 352
__global__ __launch_bounds__(SPT, 2) void spatial_attn_kernel(
    const float* __restrict__ qkv, const float* __restrict__ bias,
    float* __restrict__ out)
{
    extern __shared__ float sm[];
    float* ks = sm;                    // [NS*16]
    float* vs = sm + NS * HD;          // [NS*16]
    float* sb = sm + 2 * NS * HD;      // [NS][33] bias tile (padded)
    const int bt = blockIdx.x;
    const int h  = blockIdx.y;
    const int m0 = bt * NS;
    const int tid = threadIdx.x;

    for (int idx = tid; idx < NS * HD; idx += SPT) {
        const int j = idx >> 4, d = idx & 15;
        const float* row = qkv + (size_t)(m0 + j) * D3 + h * HD + d;
        ks[j * 16 + d] = row[DD];
        vs[j * 16 + d] = row[2 * DD];
    }

    const int q = tid;
    ull q2[8];
    if (q < NS) {
        const float* qr = qkv + (size_t)(m0 + q) * D3 + h * HD;
        #pragma unroll
        for (int p = 0; p < 8; p++) q2[p] = pack2(qr[2*p], qr[2*p+1]);
    }
    ull o2[8];
    #pragma unroll
    for (int p = 0; p < 8; p++) o2[p] = 0ull;
    float lsum = 0.f;

    for (int jt = 0; jt < NS; jt += 32) {
        __syncthreads();
        for (int idx = tid; idx < NS * 32; idx += SPT) {
            const int r = idx >> 5, c = idx & 31;
            const int jj = jt + c;
            sb[r * 33 + c] = (jj < NS) ? bias[r * NS + jj] : 0.f;
        }
        __syncthreads();
        if (q < NS) {
            const int jmax = (NS - jt < 32) ? (NS - jt) : 32;
            for (int jl = 0; jl < jmax; jl++) {
                const int j = jt + jl;
                const ulonglong2* kp = (const ulonglong2*)(ks + j * 16);
                ulonglong2 k01 = kp[0], k23 = kp[1];
                ull acc = 0ull;
                ffma2(acc, q2[0], k01.x); ffma2(acc, q2[1], k01.y);
                ffma2(acc, q2[2], k23.x); ffma2(acc, q2[3], k23.y);
                ulonglong2 k45 = kp[2], k67 = kp[3];
                ffma2(acc, q2[4], k45.x); ffma2(acc, q2[5], k45.y);
                ffma2(acc, q2[6], k67.x); ffma2(acc, q2[7], k67.y);
                float2 sp = unpack2(acc);
                const float s = (sp.x + sp.y) * 0.25f + sb[q * 33 + jl];
                const float e = __expf(s);
                lsum += e;
                const ull ee = splat2(e);
                const ulonglong2* vp = (const ulonglong2*)(vs + j * 16);
                ulonglong2 v01 = vp[0], v23 = vp[1];
                ffma2(o2[0], ee, v01.x); ffma2(o2[1], ee, v01.y);
                ffma2(o2[2], ee, v23.x); ffma2(o2[3], ee, v23.y);
                ulonglong2 v45 = vp[2], v67 = vp[3];
                ffma2(o2[4], ee, v45.x); ffma2(o2[5], ee, v45.y);
                ffma2(o2[6], ee, v67.x); ffma2(o2[7], ee, v67.y);
            }
        }
    }

    if (q < NS) {
        const float inv = 1.f / lsum;
        float o[16];
        #pragma unroll
        for (int p = 0; p < 8; p++) {
            float2 f = unpack2(o2[p]);
            o[2*p]   = f.x * inv;
            o[2*p+1] = f.y * inv;
        }
        float* op = out + (size_t)(m0 + q) * DD + h * HD;
        #pragma unroll
        for (int d = 0; d < 16; d += 4)
            *(float4*)(op + d) = make_float4(o[d], o[d+1], o[d+2], o[d+3]);
    }
}

#define SP_SMEM (2 * NS * HD * 4 + NS * 33 * 4)   // 41600 + 42900 = 84500 B

// ---------------- launch ---------------------------------------------------
extern "C" void kernel_launch(void* const* d_in, const int* in_sizes, int n_in,
                              void* d_out, int out_size)
{
    const float* x       = (const float*)d_in[0];
    const float* t_w_in  = (const float*)d_in[1];
    const float* t_b_in  = (const float*)d_in[2];
    const float* t_w_out = (const float*)d_in[3];
    const float* t_b_out = (const float*)d_in[4];
    const float* s_w_in  = (const float*)d_in[5];
    const float* s_b_in  = (const float*)d_in[6];
    const float* s_w_out = (const float*)d_in[7];
    const float* s_b_out = (const float*)d_in[8];
    const float* gbias   = (const float*)d_in[9];
    const float* nt_g    = (const float*)d_in[10];
    const float* nt_b    = (const float*)d_in[11];
    const float* ns_g    = (const float*)d_in[12];
    const float* ns_b    = (const float*)d_in[13];
    const float* ff_w1   = (const float*)d_in[14];
    const float* ff_b1   = (const float*)d_in[15];
    const float* ff_w2   = (const float*)d_in[16];
    const float* ff_b2   = (const float*)d_in[17];
    const float* nf_g    = (const float*)d_in[18];
    const float* nf_b    = (const float*)d_in[19];
    float* out = (float*)d_out;

    float *qkv, *attn, *x1, *x2, *hid;
    cudaGetSymbolAddress((void**)&qkv,  g_qkv);
    cudaGetSymbolAddress((void**)&attn, g_attn);
    cudaGetSymbolAddress((void**)&x1,   g_x1);
    cudaGetSymbolAddress((void**)&x2,   g_x2);
    cudaGetSymbolAddress((void**)&hid,  g_hid);

    cudaFuncSetAttribute(spatial_attn_kernel,
                         cudaFuncAttributeMaxDynamicSharedMemorySize, SP_SMEM);

    const int M = MTOK;          // 124800 = 975 * 128
    const dim3 g128(128);

    // 1) temporal QKV projection  [M,128] @ [384,128]^T
    gemm_nt_kernel<0><<<dim3(D3/128, M/128), g128>>>(x, t_w_in, t_b_in, qkv, M, D3, DD);
    // 2) temporal attention
    temporal_attn_kernel<<<BB * NS, 256>>>(qkv, attn);
    // 3) temporal out-proj + residual(x) + LN  -> x1
    gemm_nt_ln_kernel<<<M/128, g128>>>(attn, t_w_out, t_b_out, x, nt_g, nt_b, x1, M, DD);
    // 4) spatial QKV projection
    gemm_nt_kernel<0><<<dim3(D3/128, M/128), g128>>>(x1, s_w_in, s_b_in, qkv, M, D3, DD);
    // 5) spatial attention with graph bias
    spatial_attn_kernel<<<dim3(BB*TT, HH), SPT, SP_SMEM>>>(qkv, gbias, attn);
    // 6) spatial out-proj + residual(x1) + LN -> x2
    gemm_nt_ln_kernel<<<M/128, g128>>>(attn, s_w_out, s_b_out, x1, ns_g, ns_b, x2, M, DD);
    // 7) FFN up + GELU  [M,128] @ [512,128]^T
    gemm_nt_kernel<1><<<dim3(FF/128, M/128), g128>>>(x2, ff_w1, ff_b1, hid, M, FF, DD);
    // 8) FFN down + residual(x2) + LN -> output
    gemm_nt_ln_kernel<<<M/128, g128>>>(hid, ff_w2, ff_b2, x2, nf_g, nf_b, out, M, FF);
}

// round 7
// speedup vs baseline: 1.3070x; 1.0012x over previous
#include <cuda_runtime.h>
#include <math.h>

// Problem dims (fixed by reference setup_inputs)
#define BB 32
#define TT 12
#define NS 325          // sensors
#define DD 128
#define HH 8
#define HD 16
#define FF 512
#define D3 384
#define MTOK (BB*TT*NS) // 124800 tokens

typedef unsigned long long ull;

// ---------------- f32x2 packed-FMA helpers (Blackwell FFMA2) ---------------
__device__ __forceinline__ ull splat2(float x) {
    ull r; asm("mov.b64 %0, {%1, %1};" : "=l"(r) : "f"(x)); return r;
}
__device__ __forceinline__ ull pack2(float x, float y) {
    ull r; asm("mov.b64 %0, {%1, %2};" : "=l"(r) : "f"(x), "f"(y)); return r;
}
__device__ __forceinline__ void ffma2(ull& d, ull a, ull b) {
    asm("fma.rn.f32x2 %0, %1, %2, %3;" : "=l"(d) : "l"(a), "l"(b), "l"(d));
}
__device__ __forceinline__ float2 unpack2(ull r) {
    float x, y; asm("mov.b64 {%0, %1}, %2;" : "=f"(x), "=f"(y) : "l"(r));
    return make_float2(x, y);
}

// ---------------- scratch (device globals; no allocation allowed) ----------
__device__ float g_qkv [(size_t)MTOK * D3];
__device__ float g_attn[(size_t)MTOK * DD];
__device__ float g_x1  [(size_t)MTOK * DD];
__device__ float g_x2  [(size_t)MTOK * DD];
__device__ float g_hid [(size_t)MTOK * FF];

__device__ __forceinline__ float gelu_f(float v) {
    // tanh-approx GELU via sigmoid identity: 0.5v(1+tanh(u)) = v*sigmoid(2u)
    const float u2 = 1.5957691216057308f * (v + 0.044715f * v * v * v);
    return v * (1.0f / (1.0f + __expf(-u2)));
}

// =============== NT SGEMM v4: C[M,N] = A[M,K] @ W[N,K]^T + bias ============
// 128 threads, block 128x128, BK=16, DOUBLE-BUFFERED smem (1 sync per tile).
// Warps 2x2 (64x64 tiles), lanes 8(m)x4(n), microtile 8m x 16n via FFMA2.
// EPI: 0 = bias only, 1 = bias + GELU
template<int EPI>
__global__ __launch_bounds__(128, 2) void gemm_nt_kernel(
    const float* __restrict__ A, const float* __restrict__ W,
    const float* __restrict__ bias, float* __restrict__ C,
    int M, int N, int K)
{
    __shared__ float As[2][16][132];
    __shared__ float Ws[2][16][132];
    const int tid  = threadIdx.x;
    const int warp = tid >> 5, lane = tid & 31;
    const int wm = warp >> 1, wn = warp & 1;     // 2 x 2 warps
    const int lm = lane & 7,  ln = lane >> 3;    // 8 x 4 lanes
    const int ma0 = wm * 64 + lm * 4;            // rows ma0..+3
    const int ma1 = ma0 + 32;                    // rows ma1..+3
    const int nb  = wn * 64 + ln * 16;           // cols nb..+15
    const int m0 = blockIdx.y * 128;
    const int n0 = blockIdx.x * 128;

    const float* Ag = A + (size_t)(m0 + tid) * K;
    const float* Wg = W + (size_t)(n0 + tid) * K;

    ull acc2[8][8];
    #pragma unroll
    for (int i = 0; i < 8; i++)
        #pragma unroll
        for (int j = 0; j < 8; j++) acc2[i][j] = 0ull;

    float4 av[4], wv[4];
    #pragma unroll
    for (int j = 0; j < 4; j++) {
        av[j] = *(const float4*)(Ag + j * 4);
        wv[j] = *(const float4*)(Wg + j * 4);
    }
    #pragma unroll
    for (int j = 0; j < 4; j++) {
        As[0][4*j+0][tid] = av[j].x; As[0][4*j+1][tid] = av[j].y;
        As[0][4*j+2][tid] = av[j].z; As[0][4*j+3][tid] = av[j].w;
        Ws[0][4*j+0][tid] = wv[j].x; Ws[0][4*j+1][tid] = wv[j].y;
        Ws[0][4*j+2][tid] = wv[j].z; Ws[0][4*j+3][tid] = wv[j].w;
    }
    __syncthreads();

    int cur = 0;
    for (int k0 = 0; ; k0 += 16) {
        const bool more = (k0 + 16 < K);
        if (more) {
            #pragma unroll
            for (int j = 0; j < 4; j++) {
                av[j] = *(const float4*)(Ag + k0 + 16 + j * 4);
                wv[j] = *(const float4*)(Wg + k0 + 16 + j * 4);
            }
        }
        #pragma unroll
        for (int kk = 0; kk < 16; kk++) {
            float4 a0 = *(const float4*)&As[cur][kk][ma0];
            float4 a1 = *(const float4*)&As[cur][kk][ma1];
            ulonglong2 b01 = *(const ulonglong2*)&Ws[cur][kk][nb];
            ulonglong2 b23 = *(const ulonglong2*)&Ws[cur][kk][nb + 4];
            ulonglong2 b45 = *(const ulonglong2*)&Ws[cur][kk][nb + 8];
            ulonglong2 b67 = *(const ulonglong2*)&Ws[cur][kk][nb + 12];
            ull aa[8];
            aa[0]=splat2(a0.x); aa[1]=splat2(a0.y); aa[2]=splat2(a0.z); aa[3]=splat2(a0.w);
            aa[4]=splat2(a1.x); aa[5]=splat2(a1.y); aa[6]=splat2(a1.z); aa[7]=splat2(a1.w);
            ull bb[8] = {b01.x, b01.y, b23.x, b23.y, b45.x, b45.y, b67.x, b67.y};
            #pragma unroll
            for (int i = 0; i < 8; i++)
                #pragma unroll
                for (int j = 0; j < 8; j++)
                    ffma2(acc2[i][j], aa[i], bb[j]);
        }
        if (!more) break;
        const int nxt = cur ^ 1;
        #pragma unroll
        for (int j = 0; j < 4; j++) {
            As[nxt][4*j+0][tid] = av[j].x; As[nxt][4*j+1][tid] = av[j].y;
            As[nxt][4*j+2][tid] = av[j].z; As[nxt][4*j+3][tid] = av[j].w;
            Ws[nxt][4*j+0][tid] = wv[j].x; Ws[nxt][4*j+1][tid] = wv[j].y;
            Ws[nxt][4*j+2][tid] = wv[j].z; Ws[nxt][4*j+3][tid] = wv[j].w;
        }
        __syncthreads();
        cur = nxt;
    }

    float bv[16];
    #pragma unroll
    for (int j = 0; j < 16; j += 4)
        *(float4*)&bv[j] = *(const float4*)(bias + n0 + nb + j);

    #pragma unroll
    for (int i = 0; i < 8; i++) {
        const int m = m0 + ((i < 4) ? (ma0 + i) : (ma1 + i - 4));
        float o[16];
        #pragma unroll
        for (int jp = 0; jp < 8; jp++) {
            float2 f = unpack2(acc2[i][jp]);
            o[2*jp]   = f.x + bv[2*jp];
            o[2*jp+1] = f.y + bv[2*jp+1];
        }
        if (EPI == 1) {
            #pragma unroll
            for (int j = 0; j < 16; j++) o[j] = gelu_f(o[j]);
        }
        float* cp = C + (size_t)m * N + n0 + nb;
        #pragma unroll
        for (int j = 0; j < 16; j += 4)
            *(float4*)(cp + j) = make_float4(o[j], o[j+1], o[j+2], o[j+3]);
    }
}

// ========= NT SGEMM v4 fused with residual + LayerNorm. N fixed 128 ========
// out = LN(res + A@W^T + bias) * g + b. Block covers full 128-col rows.
__global__ __launch_bounds__(128, 2) void gemm_nt_ln_kernel(
    const float* __restrict__ A, const float* __restrict__ W,
    const float* __restrict__ bias, const float* __restrict__ res,
    const float* __restrict__ lng, const float* __restrict__ lnb,
    float* __restrict__ C, int M, int K)
{
    __shared__ float As[2][16][132];
    __shared__ float Ws[2][16][132];
    __shared__ float2 wred[128][2];
    const int tid  = threadIdx.x;
    const int warp = tid >> 5, lane = tid & 31;
    const int wm = warp >> 1, wn = warp & 1;
    const int lm = lane & 7,  ln = lane >> 3;
    const int ma0 = wm * 64 + lm * 4;
    const int ma1 = ma0 + 32;
    const int nb  = wn * 64 + ln * 16;
    const int m0 = blockIdx.x * 128;

    const float* Ag = A + (size_t)(m0 + tid) * K;
    const float* Wg = W + (size_t)tid * K;       // N = 128 rows exactly

    ull acc2[8][8];
    #pragma unroll
    for (int i = 0; i < 8; i++)
        #pragma unroll
        for (int j = 0; j < 8; j++) acc2[i][j] = 0ull;

    float4 av[4], wv[4];
    #pragma unroll
    for (int j = 0; j < 4; j++) {
        av[j] = *(const float4*)(Ag + j * 4);
        wv[j] = *(const float4*)(Wg + j * 4);
    }
    #pragma unroll
    for (int j = 0; j < 4; j++) {
        As[0][4*j+0][tid] = av[j].x; As[0][4*j+1][tid] = av[j].y;
        As[0][4*j+2][tid] = av[j].z; As[0][4*j+3][tid] = av[j].w;
        Ws[0][4*j+0][tid] = wv[j].x; Ws[0][4*j+1][tid] = wv[j].y;
        Ws[0][4*j+2][tid] = wv[j].z; Ws[0][4*j+3][tid] = wv[j].w;
    }
    __syncthreads();

    int cur = 0;
    for (int k0 = 0; ; k0 += 16) {
        const bool more = (k0 + 16 < K);
        if (more) {
            #pragma unroll
            for (int j = 0; j < 4; j++) {
                av[j] = *(const float4*)(Ag + k0 + 16 + j * 4);
                wv[j] = *(const float4*)(Wg + k0 + 16 + j * 4);
            }
        }
        #pragma unroll
        for (int kk = 0; kk < 16; kk++) {
            float4 a0 = *(const float4*)&As[cur][kk][ma0];
            float4 a1 = *(const float4*)&As[cur][kk][ma1];
            ulonglong2 b01 = *(const ulonglong2*)&Ws[cur][kk][nb];
            ulonglong2 b23 = *(const ulonglong2*)&Ws[cur][kk][nb + 4];
            ulonglong2 b45 = *(const ulonglong2*)&Ws[cur][kk][nb + 8];
            ulonglong2 b67 = *(const ulonglong2*)&Ws[cur][kk][nb + 12];
            ull aa[8];
            aa[0]=splat2(a0.x); aa[1]=splat2(a0.y); aa[2]=splat2(a0.z); aa[3]=splat2(a0.w);
            aa[4]=splat2(a1.x); aa[5]=splat2(a1.y); aa[6]=splat2(a1.z); aa[7]=splat2(a1.w);
            ull bb[8] = {b01.x, b01.y, b23.x, b23.y, b45.x, b45.y, b67.x, b67.y};
            #pragma unroll
            for (int i = 0; i < 8; i++)
                #pragma unroll
                for (int j = 0; j < 8; j++)
                    ffma2(acc2[i][j], aa[i], bb[j]);
        }
        if (!more) break;
        const int nxt = cur ^ 1;
        #pragma unroll
        for (int j = 0; j < 4; j++) {
            As[nxt][4*j+0][tid] = av[j].x; As[nxt][4*j+1][tid] = av[j].y;
            As[nxt][4*j+2][tid] = av[j].z; As[nxt][4*j+3][tid] = av[j].w;
            Ws[nxt][4*j+0][tid] = wv[j].x; Ws[nxt][4*j+1][tid] = wv[j].y;
            Ws[nxt][4*j+2][tid] = wv[j].z; Ws[nxt][4*j+3][tid] = wv[j].w;
        }
        __syncthreads();
        cur = nxt;
    }

    float bv[16];
    #pragma unroll
    for (int j = 0; j < 16; j += 4)
        *(float4*)&bv[j] = *(const float4*)(bias + nb + j);

    // pass 1: v = acc + bias + residual; partial sums; reduce over ln + wn
    float vrow[8][16];
    #pragma unroll
    for (int i = 0; i < 8; i++) {
        const int m = m0 + ((i < 4) ? (ma0 + i) : (ma1 + i - 4));
        const float* rp = res + (size_t)m * DD + nb;
        #pragma unroll
        for (int j = 0; j < 16; j += 4) {
            float4 r = *(const float4*)(rp + j);
            float2 f0 = unpack2(acc2[i][j/2]);
            float2 f1 = unpack2(acc2[i][j/2 + 1]);
            vrow[i][j]   = f0.x + bv[j]   + r.x;
            vrow[i][j+1] = f0.y + bv[j+1] + r.y;
            vrow[i][j+2] = f1.x + bv[j+2] + r.z;
            vrow[i][j+3] = f1.y + bv[j+3] + r.w;
        }
        float s = 0.f, s2 = 0.f;
        #pragma unroll
        for (int j = 0; j < 16; j++) { s += vrow[i][j]; s2 += vrow[i][j]*vrow[i][j]; }
        s  += __shfl_xor_sync(0xffffffffu, s,  8);
        s2 += __shfl_xor_sync(0xffffffffu, s2, 8);
        s  += __shfl_xor_sync(0xffffffffu, s,  16);
        s2 += __shfl_xor_sync(0xffffffffu, s2, 16);
        if (ln == 0) {
            const int row = (i < 4) ? (ma0 + i) : (ma1 + i - 4);
            wred[row][wn] = make_float2(s, s2);
        }
    }
    __syncthreads();

    float gv[16], lb[16];
    #pragma unroll
    for (int j = 0; j < 16; j += 4) {
        *(float4*)&gv[j] = *(const float4*)(lng + nb + j);
        *(float4*)&lb[j] = *(const float4*)(lnb + nb + j);
    }

    #pragma unroll
    for (int i = 0; i < 8; i++) {
        const int row = (i < 4) ? (ma0 + i) : (ma1 + i - 4);
        const int m = m0 + row;
        float2 p0 = wred[row][0];
        float2 p1 = wred[row][1];
        const float s  = p0.x + p1.x;
        const float s2 = p0.y + p1.y;
        const float mu  = s * (1.f / DD);
        const float var = s2 * (1.f / DD) - mu * mu;
        const float rstd = rsqrtf(var + 1e-5f);
        float* cp = C + (size_t)m * DD + nb;
        #pragma unroll
        for (int j = 0; j < 16; j += 4) {
            float4 o;
            o.x = (vrow[i][j]   - mu) * rstd * gv[j]   + lb[j];
            o.y = (vrow[i][j+1] - mu) * rstd * gv[j+1] + lb[j+1];
            o.z = (vrow[i][j+2] - mu) * rstd * gv[j+2] + lb[j+2];
            o.w = (vrow[i][j+3] - mu) * rstd * gv[j+3] + lb[j+3];
            *(float4*)(cp + j) = o;
        }
    }
}

// ---------------- temporal attention: seq = T=12 over (b, n), per head -----
__global__ __launch_bounds__(256) void temporal_attn_kernel(
    const float* __restrict__ qkv, float* __restrict__ out)
{
    __shared__ float s[TT][D3];   // 18 KB
    const int bn = blockIdx.x;
    const int b = bn / NS, n = bn % NS;

    for (int idx = threadIdx.x; idx < TT * D3; idx += 256) {
        const int t = idx / D3, c = idx % D3;
        s[t][c] = qkv[(size_t)((b * TT + t) * NS + n) * D3 + c];
    }
    __syncthreads();

    const int h = threadIdx.x >> 5;
    const int lane = threadIdx.x & 31;
    if (lane < TT) {
        const int tq = lane;
        float q[HD];
        #pragma unroll
        for (int d = 0; d < HD; d++) q[d] = s[tq][h * HD + d];

        float sc[TT];
        float mx = -1e30f;
        #pragma unroll
        for (int tk = 0; tk < TT; tk++) {
            float a = 0.f;
            #pragma unroll
            for (int d = 0; d < HD; d++) a += q[d] * s[tk][DD + h * HD + d];
            a *= 0.25f;           // 1/sqrt(16)
            sc[tk] = a;
            mx = fmaxf(mx, a);
        }
        float sum = 0.f;
        #pragma unroll
        for (int tk = 0; tk < TT; tk++) { sc[tk] = __expf(sc[tk] - mx); sum += sc[tk]; }
        const float inv = 1.f / sum;

        float o[HD];
        #pragma unroll
        for (int d = 0; d < HD; d++) o[d] = 0.f;
        #pragma unroll
        for (int tk = 0; tk < TT; tk++) {
            const float p = sc[tk] * inv;
            #pragma unroll
            for (int d = 0; d < HD; d++) o[d] += p * s[tk][2 * DD + h * HD + d];
        }
        const size_t ob = (size_t)((b * TT + tq) * NS + n) * DD + h * HD;
        #pragma unroll
        for (int d = 0; d < HD; d += 4)
            *(float4*)(out + ob + d) = make_float4(o[d], o[d+1], o[d+2], o[d+3]);
    }
}

// ---------------- spatial attention v2: lane-owns-query, no shuffles -------
#define SPT 352
__global__ __launch_bounds__(SPT, 2) void spatial_attn_kernel(
    const float* __restrict__ qkv, const float* __restrict__ bias,
    float* __restrict__ out)
{
    extern __shared__ float sm[];
    float* ks = sm;                    // [NS*16]
    float* vs = sm + NS * HD;          // [NS*16]
    float* sb = sm + 2 * NS * HD;      // [NS][33] bias tile (padded)
    const int bt = blockIdx.x;
    const int h  = blockIdx.y;
    const int m0 = bt * NS;
    const int tid = threadIdx.x;

    for (int idx = tid; idx < NS * HD; idx += SPT) {
        const int j = idx >> 4, d = idx & 15;
        const float* row = qkv + (size_t)(m0 + j) * D3 + h * HD + d;
        ks[j * 16 + d] = row[DD];
        vs[j * 16 + d] = row[2 * DD];
    }

    const int q = tid;
    ull q2[8];
    if (q < NS) {
        const float* qr = qkv + (size_t)(m0 + q) * D3 + h * HD;
        #pragma unroll
        for (int p = 0; p < 8; p++) q2[p] = pack2(qr[2*p], qr[2*p+1]);
    }
    ull o2[8];
    #pragma unroll
    for (int p = 0; p < 8; p++) o2[p] = 0ull;
    float lsum = 0.f;

    for (int jt = 0; jt < NS; jt += 32) {
        __syncthreads();
        for (int idx = tid; idx < NS * 32; idx += SPT) {
            const int r = idx >> 5, c = idx & 31;
            const int jj = jt + c;
            sb[r * 33 + c] = (jj < NS) ? bias[r * NS + jj] : 0.f;
        }
        __syncthreads();
        if (q < NS) {
            const int jmax = (NS - jt < 32) ? (NS - jt) : 32;
            for (int jl = 0; jl < jmax; jl++) {
                const int j = jt + jl;
                const ulonglong2* kp = (const ulonglong2*)(ks + j * 16);
                ulonglong2 k01 = kp[0], k23 = kp[1];
                ull acc = 0ull;
                ffma2(acc, q2[0], k01.x); ffma2(acc, q2[1], k01.y);
                ffma2(acc, q2[2], k23.x); ffma2(acc, q2[3], k23.y);
                ulonglong2 k45 = kp[2], k67 = kp[3];
                ffma2(acc, q2[4], k45.x); ffma2(acc, q2[5], k45.y);
                ffma2(acc, q2[6], k67.x); ffma2(acc, q2[7], k67.y);
                float2 sp = unpack2(acc);
                const float s = (sp.x + sp.y) * 0.25f + sb[q * 33 + jl];
                const float e = __expf(s);
                lsum += e;
                const ull ee = splat2(e);
                const ulonglong2* vp = (const ulonglong2*)(vs + j * 16);
                ulonglong2 v01 = vp[0], v23 = vp[1];
                ffma2(o2[0], ee, v01.x); ffma2(o2[1], ee, v01.y);
                ffma2(o2[2], ee, v23.x); ffma2(o2[3], ee, v23.y);
                ulonglong2 v45 = vp[2], v67 = vp[3];
                ffma2(o2[4], ee, v45.x); ffma2(o2[5], ee, v45.y);
                ffma2(o2[6], ee, v67.x); ffma2(o2[7], ee, v67.y);
            }
        }
    }

    if (q < NS) {
        const float inv = 1.f / lsum;
        float o[16];
        #pragma unroll
        for (int p = 0; p < 8; p++) {
            float2 f = unpack2(o2[p]);
            o[2*p]   = f.x * inv;
            o[2*p+1] = f.y * inv;
        }
        float* op = out + (size_t)(m0 + q) * DD + h * HD;
        #pragma unroll
        for (int d = 0; d < 16; d += 4)
            *(float4*)(op + d) = make_float4(o[d], o[d+1], o[d+2], o[d+3]);
    }
}

#define SP_SMEM (2 * NS * HD * 4 + NS * 33 * 4)   // 41600 + 42900 = 84500 B

// ---------------- launch ---------------------------------------------------
extern "C" void kernel_launch(void* const* d_in, const int* in_sizes, int n_in,
                              void* d_out, int out_size)
{
    const float* x       = (const float*)d_in[0];
    const float* t_w_in  = (const float*)d_in[1];
    const float* t_b_in  = (const float*)d_in[2];
    const float* t_w_out = (const float*)d_in[3];
    const float* t_b_out = (const float*)d_in[4];
    const float* s_w_in  = (const float*)d_in[5];
    const float* s_b_in  = (const float*)d_in[6];
    const float* s_w_out = (const float*)d_in[7];
    const float* s_b_out = (const float*)d_in[8];
    const float* gbias   = (const float*)d_in[9];
    const float* nt_g    = (const float*)d_in[10];
    const float* nt_b    = (const float*)d_in[11];
    const float* ns_g    = (const float*)d_in[12];
    const float* ns_b    = (const float*)d_in[13];
    const float* ff_w1   = (const float*)d_in[14];
    const float* ff_b1   = (const float*)d_in[15];
    const float* ff_w2   = (const float*)d_in[16];
    const float* ff_b2   = (const float*)d_in[17];
    const float* nf_g    = (const float*)d_in[18];
    const float* nf_b    = (const float*)d_in[19];
    float* out = (float*)d_out;

    float *qkv, *attn, *x1, *x2, *hid;
    cudaGetSymbolAddress((void**)&qkv,  g_qkv);
    cudaGetSymbolAddress((void**)&attn, g_attn);
    cudaGetSymbolAddress((void**)&x1,   g_x1);
    cudaGetSymbolAddress((void**)&x2,   g_x2);
    cudaGetSymbolAddress((void**)&hid,  g_hid);

    cudaFuncSetAttribute(spatial_attn_kernel,
                         cudaFuncAttributeMaxDynamicSharedMemorySize, SP_SMEM);

    const int M = MTOK;          // 124800 = 975 * 128
    const dim3 g128(128);

    // 1) temporal QKV projection  [M,128] @ [384,128]^T
    gemm_nt_kernel<0><<<dim3(D3/128, M/128), g128>>>(x, t_w_in, t_b_in, qkv, M, D3, DD);
    // 2) temporal attention
    temporal_attn_kernel<<<BB * NS, 256>>>(qkv, attn);
    // 3) temporal out-proj + residual(x) + LN  -> x1
    gemm_nt_ln_kernel<<<M/128, g128>>>(attn, t_w_out, t_b_out, x, nt_g, nt_b, x1, M, DD);
    // 4) spatial QKV projection
    gemm_nt_kernel<0><<<dim3(D3/128, M/128), g128>>>(x1, s_w_in, s_b_in, qkv, M, D3, DD);
    // 5) spatial attention with graph bias
    spatial_attn_kernel<<<dim3(BB*TT, HH), SPT, SP_SMEM>>>(qkv, gbias, attn);
    // 6) spatial out-proj + residual(x1) + LN -> x2
    gemm_nt_ln_kernel<<<M/128, g128>>>(attn, s_w_out, s_b_out, x1, ns_g, ns_b, x2, M, DD);
    // 7) FFN up + GELU  [M,128] @ [512,128]^T
    gemm_nt_kernel<1><<<dim3(FF/128, M/128), g128>>>(x2, ff_w1, ff_b1, hid, M, FF, DD);
    // 8) FFN down + residual(x2) + LN -> output
    gemm_nt_ln_kernel<<<M/128, g128>>>(hid, ff_w2, ff_b2, x2, nf_g, nf_b, out, M, FF);
}

// round 14
// speedup vs baseline: 1.6944x; 1.2964x over previous
#include <cuda_runtime.h>
#include <cuda_bf16.h>
#include <math.h>

// Problem dims (fixed by reference setup_inputs)
#define BB 32
#define TT 12
#define NS 325
#define DD 128
#define HH 8
#define HD 16
#define FF 512
#define D3 384
#define MTOK (BB*TT*NS)   // 124800 tokens

typedef unsigned int uint32;
typedef unsigned long long ull;
typedef __nv_bfloat16 bf16;

// ---------------- f32x2 helpers (attention kernels) ------------------------
__device__ __forceinline__ ull splat2(float x) {
    ull r; asm("mov.b64 %0, {%1, %1};" : "=l"(r) : "f"(x)); return r;
}
__device__ __forceinline__ ull pack2(float x, float y) {
    ull r; asm("mov.b64 %0, {%1, %2};" : "=l"(r) : "f"(x), "f"(y)); return r;
}
__device__ __forceinline__ void ffma2(ull& d, ull a, ull b) {
    asm("fma.rn.f32x2 %0, %1, %2, %3;" : "=l"(d) : "l"(a), "l"(b), "l"(d));
}
__device__ __forceinline__ float2 unpack2(ull r) {
    float x, y; asm("mov.b64 {%0, %1}, %2;" : "=f"(x), "=f"(y) : "l"(r));
    return make_float2(x, y);
}

// ---------------- scratch (device globals; no allocation allowed) ----------
__device__ float g_qkv [(size_t)MTOK * D3];
__device__ float g_attn[(size_t)MTOK * DD];
__device__ float g_x1  [(size_t)MTOK * DD];
__device__ float g_x2  [(size_t)MTOK * DD];
__device__ bf16 g_ahi[(size_t)MTOK * FF];
__device__ bf16 g_alo[(size_t)MTOK * FF];
__device__ bf16 g_bhi[(size_t)MTOK * FF];
__device__ bf16 g_blo[(size_t)MTOK * FF];
__device__ bf16 g_whi[FF * DD];
__device__ bf16 g_wlo[FF * DD];

__device__ __forceinline__ float gelu_f(float v) {
    const float u2 = 1.5957691216057308f * (v + 0.044715f * v * v * v);
    return v * (1.0f / (1.0f + __expf(-u2)));
}

__device__ __forceinline__ uint32 smem_u32(const void* p) {
    uint32 a;
    asm("{ .reg .u64 t; cvta.to.shared.u64 t, %1; cvt.u32.u64 %0, t; }"
        : "=r"(a) : "l"(p));
    return a;
}

// ---------------- baseline tensor-core primitives (sm_80+ PTX) -------------
#define LDSM4(R, addr) \
    asm volatile("ldmatrix.sync.aligned.m8n8.x4.shared.b16 {%0,%1,%2,%3}, [%4];" \
        : "=r"((R)[0]), "=r"((R)[1]), "=r"((R)[2]), "=r"((R)[3]) : "r"(addr))

#define MMA16816(D, A, B0, B1) \
    asm volatile("mma.sync.aligned.m16n8k16.row.col.f32.bf16.bf16.f32 " \
        "{%0,%1,%2,%3}, {%4,%5,%6,%7}, {%8,%9}, {%0,%1,%2,%3};" \
        : "+f"((D)[0]), "+f"((D)[1]), "+f"((D)[2]), "+f"((D)[3]) \
        : "r"((A)[0]), "r"((A)[1]), "r"((A)[2]), "r"((A)[3]), "r"(B0), "r"(B1))

// ---------------- split fp32 -> bf16 (hi, lo) ------------------------------
__global__ __launch_bounds__(256) void split_kernel(
    const float* __restrict__ in, bf16* __restrict__ hi,
    bf16* __restrict__ lo, int n)
{
    const int base = (blockIdx.x * 256 + threadIdx.x) * 4;
    if (base >= n) return;
    float4 v = *(const float4*)(in + base);
    bf16 h0 = __float2bfloat16(v.x);
    bf16 h1 = __float2bfloat16(v.y);
    bf16 h2 = __float2bfloat16(v.z);
    bf16 h3 = __float2bfloat16(v.w);
    bf16 l0 = __float2bfloat16(v.x - __bfloat162float(h0));
    bf16 l1 = __float2bfloat16(v.y - __bfloat162float(h1));
    bf16 l2 = __float2bfloat16(v.z - __bfloat162float(h2));
    bf16 l3 = __float2bfloat16(v.w - __bfloat162float(h3));
    *(__nv_bfloat162*)(hi + base)     = __nv_bfloat162(h0, h1);
    *(__nv_bfloat162*)(hi + base + 2) = __nv_bfloat162(h2, h3);
    *(__nv_bfloat162*)(lo + base)     = __nv_bfloat162(l0, l1);
    *(__nv_bfloat162*)(lo + base + 2) = __nv_bfloat162(l2, l3);
}

// =============== HMMA GEMM: C[M,N] = A[M,K] @ W[N,K]^T + bias ==============
// 256 threads, block 128x128, BK=32. Warps 2(m)x4(n), warp tile 64x32.
// mma.sync m16n8k16 bf16, 3-product split: Ahi*Whi + Alo*Whi + Ahi*Wlo.
// smem rows padded to 40 bf16 (80 B) -> conflict-free ldmatrix.
// EPI: 0 = bias (fp32), 1 = bias+GELU (bf16 hi/lo), 2 = bias+res+LN (N=128).
#define TS 40

template<int EPI>
__global__ __launch_bounds__(256, 2) void hmma_gemm(
    const bf16* __restrict__ Ahi, const bf16* __restrict__ Alo,
    const bf16* __restrict__ Whi, const bf16* __restrict__ Wlo,
    const float* __restrict__ bias, const float* __restrict__ res,
    const float* __restrict__ lng, const float* __restrict__ lnb,
    float* __restrict__ C, bf16* __restrict__ Chi, bf16* __restrict__ Clo,
    int M, int N, int K)
{
    __shared__ bf16 sAh[128 * TS], sAl[128 * TS], sWh[128 * TS], sWl[128 * TS];
    __shared__ float2 wred[128][4];
    const int tid = threadIdx.x, warp = tid >> 5, lane = tid & 31;
    const int wm = warp >> 2, wn = warp & 3;
    const int m0 = blockIdx.y * 128, n0 = blockIdx.x * 128;
    const int g = lane >> 2, t = lane & 3;

    float acc[4][4][4];
    #pragma unroll
    for (int i = 0; i < 4; i++)
        #pragma unroll
        for (int j = 0; j < 4; j++)
            #pragma unroll
            for (int r = 0; r < 4; r++) acc[i][j][r] = 0.f;

    // lane-dependent ldmatrix byte addresses (k=0 position)
    uint32 adAh[4], adAl[4], adWh[2], adWl[2];
    {
        const int arow = (lane & 15), ak = (lane >> 4) * 8;
        #pragma unroll
        for (int mt = 0; mt < 4; mt++) {
            const uint32 off = ((wm * 64 + mt * 16 + arow) * TS + ak) * 2;
            adAh[mt] = smem_u32(sAh) + off;
            adAl[mt] = smem_u32(sAl) + off;
        }
        const int brow = (lane & 7) + (lane >> 4) * 8, bk = ((lane >> 3) & 1) * 8;
        #pragma unroll
        for (int ng = 0; ng < 2; ng++) {
            const uint32 off = ((wn * 32 + ng * 16 + brow) * TS + bk) * 2;
            adWh[ng] = smem_u32(sWh) + off;
            adWl[ng] = smem_u32(sWl) + off;
        }
    }

    for (int k0 = 0; k0 < K; k0 += 32) {
        __syncthreads();
        #pragma unroll
        for (int l = 0; l < 2; l++) {
            const int idx = tid + l * 256;
            const int row = idx >> 2, co = (idx & 3) * 8;
            *(uint4*)(sAh + row * TS + co) =
                *(const uint4*)(Ahi + (size_t)(m0 + row) * K + k0 + co);
            *(uint4*)(sAl + row * TS + co) =
                *(const uint4*)(Alo + (size_t)(m0 + row) * K + k0 + co);
            *(uint4*)(sWh + row * TS + co) =
                *(const uint4*)(Whi + (size_t)(n0 + row) * K + k0 + co);
            *(uint4*)(sWl + row * TS + co) =
                *(const uint4*)(Wlo + (size_t)(n0 + row) * K + k0 + co);
        }
        __syncthreads();

        #pragma unroll
        for (int kk = 0; kk < 2; kk++) {
            const uint32 kb = kk * 32;   // 16 bf16 = 32 bytes
            uint32 a[4][4], b[2][4], tmp[4][4];
            #pragma unroll
            for (int mt = 0; mt < 4; mt++) LDSM4(a[mt], adAh[mt] + kb);
            #pragma unroll
            for (int ng = 0; ng < 2; ng++) LDSM4(b[ng], adWh[ng] + kb);
            #pragma unroll
            for (int mt = 0; mt < 4; mt++)
                #pragma unroll
                for (int nt = 0; nt < 4; nt++)
                    MMA16816(acc[mt][nt], a[mt],
                             b[nt >> 1][(nt & 1) * 2], b[nt >> 1][(nt & 1) * 2 + 1]);
            #pragma unroll
            for (int mt = 0; mt < 4; mt++) LDSM4(tmp[mt], adAl[mt] + kb);
            #pragma unroll
            for (int mt = 0; mt < 4; mt++)
                #pragma unroll
                for (int nt = 0; nt < 4; nt++)
                    MMA16816(acc[mt][nt], tmp[mt],
                             b[nt >> 1][(nt & 1) * 2], b[nt >> 1][(nt & 1) * 2 + 1]);
            #pragma unroll
            for (int ng = 0; ng < 2; ng++) LDSM4(b[ng], adWl[ng] + kb);
            #pragma unroll
            for (int mt = 0; mt < 4; mt++)
                #pragma unroll
                for (int nt = 0; nt < 4; nt++)
                    MMA16816(acc[mt][nt], a[mt],
                             b[nt >> 1][(nt & 1) * 2], b[nt >> 1][(nt & 1) * 2 + 1]);
        }
    }

    // ---------------- epilogues ----------------
    if (EPI == 0) {
        #pragma unroll
        for (int mt = 0; mt < 4; mt++) {
            const int r0 = m0 + wm * 64 + mt * 16 + g;
            #pragma unroll
            for (int nt = 0; nt < 4; nt++) {
                const int col = n0 + wn * 32 + nt * 8 + t * 2;
                const float b0 = bias[col], b1 = bias[col + 1];
                *(float2*)(C + (size_t)r0 * N + col) =
                    make_float2(acc[mt][nt][0] + b0, acc[mt][nt][1] + b1);
                *(float2*)(C + (size_t)(r0 + 8) * N + col) =
                    make_float2(acc[mt][nt][2] + b0, acc[mt][nt][3] + b1);
            }
        }
    } else if (EPI == 1) {
        #pragma unroll
        for (int mt = 0; mt < 4; mt++) {
            const int r0 = m0 + wm * 64 + mt * 16 + g;
            #pragma unroll
            for (int nt = 0; nt < 4; nt++) {
                const int col = n0 + wn * 32 + nt * 8 + t * 2;
                const float b0 = bias[col], b1 = bias[col + 1];
                #pragma unroll
                for (int h = 0; h < 2; h++) {
                    const int r = r0 + h * 8;
                    float v0 = gelu_f(acc[mt][nt][h * 2]     + b0);
                    float v1 = gelu_f(acc[mt][nt][h * 2 + 1] + b1);
                    bf16 h0 = __float2bfloat16(v0);
                    bf16 h1 = __float2bfloat16(v1);
                    bf16 l0 = __float2bfloat16(v0 - __bfloat162float(h0));
                    bf16 l1 = __float2bfloat16(v1 - __bfloat162float(h1));
                    *(__nv_bfloat162*)(Chi + (size_t)r * N + col) = __nv_bfloat162(h0, h1);
                    *(__nv_bfloat162*)(Clo + (size_t)r * N + col) = __nv_bfloat162(l0, l1);
                }
            }
        }
    } else {
        // EPI 2: bias + residual + LayerNorm over N=128 (n0 == 0)
        #pragma unroll
        for (int mt = 0; mt < 4; mt++) {
            const int lr0 = wm * 64 + mt * 16 + g;
            const int r0 = m0 + lr0;
            float s0 = 0.f, q0 = 0.f, s1 = 0.f, q1 = 0.f;
            #pragma unroll
            for (int nt = 0; nt < 4; nt++) {
                const int col = wn * 32 + nt * 8 + t * 2;
                const float b0 = bias[col], b1 = bias[col + 1];
                float2 rv0 = *(const float2*)(res + (size_t)r0 * DD + col);
                float2 rv1 = *(const float2*)(res + (size_t)(r0 + 8) * DD + col);
                float v00 = acc[mt][nt][0] + b0 + rv0.x;
                float v01 = acc[mt][nt][1] + b1 + rv0.y;
                float v10 = acc[mt][nt][2] + b0 + rv1.x;
                float v11 = acc[mt][nt][3] + b1 + rv1.y;
                s0 += v00 + v01; q0 += v00 * v00 + v01 * v01;
                s1 += v10 + v11; q1 += v10 * v10 + v11 * v11;
            }
            s0 += __shfl_xor_sync(0xffffffffu, s0, 1);
            q0 += __shfl_xor_sync(0xffffffffu, q0, 1);
            s1 += __shfl_xor_sync(0xffffffffu, s1, 1);
            q1 += __shfl_xor_sync(0xffffffffu, q1, 1);
            s0 += __shfl_xor_sync(0xffffffffu, s0, 2);
            q0 += __shfl_xor_sync(0xffffffffu, q0, 2);
            s1 += __shfl_xor_sync(0xffffffffu, s1, 2);
            q1 += __shfl_xor_sync(0xffffffffu, q1, 2);
            if (t == 0) {
                wred[lr0][wn]     = make_float2(s0, q0);
                wred[lr0 + 8][wn] = make_float2(s1, q1);
            }
        }
        __syncthreads();
        #pragma unroll
        for (int mt = 0; mt < 4; mt++) {
            const int lr0 = wm * 64 + mt * 16 + g;
            const int r0 = m0 + lr0;
            float2 p;
            float sa = 0.f, qa = 0.f, sb = 0.f, qb = 0.f;
            #pragma unroll
            for (int w = 0; w < 4; w++) {
                p = wred[lr0][w];     sa += p.x; qa += p.y;
                p = wred[lr0 + 8][w]; sb += p.x; qb += p.y;
            }
            const float mu0 = sa * (1.f / DD);
            const float rs0 = rsqrtf(qa * (1.f / DD) - mu0 * mu0 + 1e-5f);
            const float mu1 = sb * (1.f / DD);
            const float rs1 = rsqrtf(qb * (1.f / DD) - mu1 * mu1 + 1e-5f);
            #pragma unroll
            for (int nt = 0; nt < 4; nt++) {
                const int col = wn * 32 + nt * 8 + t * 2;
                const float b0 = bias[col], b1 = bias[col + 1];
                const float g0 = lng[col], g1 = lng[col + 1];
                const float e0 = lnb[col], e1 = lnb[col + 1];
                float2 rv0 = *(const float2*)(res + (size_t)r0 * DD + col);
                float2 rv1 = *(const float2*)(res + (size_t)(r0 + 8) * DD + col);
                float v00 = acc[mt][nt][0] + b0 + rv0.x;
                float v01 = acc[mt][nt][1] + b1 + rv0.y;
                float v10 = acc[mt][nt][2] + b0 + rv1.x;
                float v11 = acc[mt][nt][3] + b1 + rv1.y;
                *(float2*)(C + (size_t)r0 * DD + col) =
                    make_float2((v00 - mu0) * rs0 * g0 + e0, (v01 - mu0) * rs0 * g1 + e1);
                *(float2*)(C + (size_t)(r0 + 8) * DD + col) =
                    make_float2((v10 - mu1) * rs1 * g0 + e0, (v11 - mu1) * rs1 * g1 + e1);
            }
        }
    }
}

// ---------------- temporal attention (unchanged) ---------------------------
__global__ __launch_bounds__(256) void temporal_attn_kernel(
    const float* __restrict__ qkv, float* __restrict__ out)
{
    __shared__ float s[TT][D3];
    const int bn = blockIdx.x;
    const int b = bn / NS, n = bn % NS;

    for (int idx = threadIdx.x; idx < TT * D3; idx += 256) {
        const int tt = idx / D3, c = idx % D3;
        s[tt][c] = qkv[(size_t)((b * TT + tt) * NS + n) * D3 + c];
    }
    __syncthreads();

    const int h = threadIdx.x >> 5;
    const int lane = threadIdx.x & 31;
    if (lane < TT) {
        const int tq = lane;
        float q[HD];
        #pragma unroll
        for (int d = 0; d < HD; d++) q[d] = s[tq][h * HD + d];

        float sc[TT];
        float mx = -1e30f;
        #pragma unroll
        for (int tk = 0; tk < TT; tk++) {
            float a = 0.f;
            #pragma unroll
            for (int d = 0; d < HD; d++) a += q[d] * s[tk][DD + h * HD + d];
            a *= 0.25f;
            sc[tk] = a;
            mx = fmaxf(mx, a);
        }
        float sum = 0.f;
        #pragma unroll
        for (int tk = 0; tk < TT; tk++) { sc[tk] = __expf(sc[tk] - mx); sum += sc[tk]; }
        const float inv = 1.f / sum;

        float o[HD];
        #pragma unroll
        for (int d = 0; d < HD; d++) o[d] = 0.f;
        #pragma unroll
        for (int tk = 0; tk < TT; tk++) {
            const float p = sc[tk] * inv;
            #pragma unroll
            for (int d = 0; d < HD; d++) o[d] += p * s[tk][2 * DD + h * HD + d];
        }
        const size_t ob = (size_t)((b * TT + tq) * NS + n) * DD + h * HD;
        #pragma unroll
        for (int d = 0; d < HD; d += 4)
            *(float4*)(out + ob + d) = make_float4(o[d], o[d+1], o[d+2], o[d+3]);
    }
}

// ---------------- spatial attention (unchanged) ----------------------------
#define SPT 352
__global__ __launch_bounds__(SPT, 2) void spatial_attn_kernel(
    const float* __restrict__ qkv, const float* __restrict__ bias,
    float* __restrict__ out)
{
    extern __shared__ float smf[];
    float* ks = smf;
    float* vs = smf + NS * HD;
    float* sbuf = smf + 2 * NS * HD;
    const int bt = blockIdx.x;
    const int h  = blockIdx.y;
    const int m0 = bt * NS;
    const int tid = threadIdx.x;

    for (int idx = tid; idx < NS * HD; idx += SPT) {
        const int j = idx >> 4, d = idx & 15;
        const float* row = qkv + (size_t)(m0 + j) * D3 + h * HD + d;
        ks[j * 16 + d] = row[DD];
        vs[j * 16 + d] = row[2 * DD];
    }

    const int q = tid;
    ull q2[8];
    if (q < NS) {
        const float* qr = qkv + (size_t)(m0 + q) * D3 + h * HD;
        #pragma unroll
        for (int p = 0; p < 8; p++) q2[p] = pack2(qr[2*p], qr[2*p+1]);
    }
    ull o2[8];
    #pragma unroll
    for (int p = 0; p < 8; p++) o2[p] = 0ull;
    float lsum = 0.f;

    for (int jt = 0; jt < NS; jt += 32) {
        __syncthreads();
        for (int idx = tid; idx < NS * 32; idx += SPT) {
            const int r = idx >> 5, c = idx & 31;
            const int jj = jt + c;
            sbuf[r * 33 + c] = (jj < NS) ? bias[r * NS + jj] : 0.f;
        }
        __syncthreads();
        if (q < NS) {
            const int jmax = (NS - jt < 32) ? (NS - jt) : 32;
            for (int jl = 0; jl < jmax; jl++) {
                const int j = jt + jl;
                const ulonglong2* kp = (const ulonglong2*)(ks + j * 16);
                ulonglong2 k01 = kp[0], k23 = kp[1];
                ull acc = 0ull;
                ffma2(acc, q2[0], k01.x); ffma2(acc, q2[1], k01.y);
                ffma2(acc, q2[2], k23.x); ffma2(acc, q2[3], k23.y);
                ulonglong2 k45 = kp[2], k67 = kp[3];
                ffma2(acc, q2[4], k45.x); ffma2(acc, q2[5], k45.y);
                ffma2(acc, q2[6], k67.x); ffma2(acc, q2[7], k67.y);
                float2 sp = unpack2(acc);
                const float s = (sp.x + sp.y) * 0.25f + sbuf[q * 33 + jl];
                const float e = __expf(s);
                lsum += e;
                const ull ee = splat2(e);
                const ulonglong2* vp = (const ulonglong2*)(vs + j * 16);
                ulonglong2 v01 = vp[0], v23 = vp[1];
                ffma2(o2[0], ee, v01.x); ffma2(o2[1], ee, v01.y);
                ffma2(o2[2], ee, v23.x); ffma2(o2[3], ee, v23.y);
                ulonglong2 v45 = vp[2], v67 = vp[3];
                ffma2(o2[4], ee, v45.x); ffma2(o2[5], ee, v45.y);
                ffma2(o2[6], ee, v67.x); ffma2(o2[7], ee, v67.y);
            }
        }
    }

    if (q < NS) {
        const float inv = 1.f / lsum;
        float o[16];
        #pragma unroll
        for (int p = 0; p < 8; p++) {
            float2 f = unpack2(o2[p]);
            o[2*p]   = f.x * inv;
            o[2*p+1] = f.y * inv;
        }
        float* op = out + (size_t)(m0 + q) * DD + h * HD;
        #pragma unroll
        for (int d = 0; d < 16; d += 4)
            *(float4*)(op + d) = make_float4(o[d], o[d+1], o[d+2], o[d+3]);
    }
}

#define SP_SMEM (2 * NS * HD * 4 + NS * 33 * 4)

// ---------------- launch ---------------------------------------------------
extern "C" void kernel_launch(void* const* d_in, const int* in_sizes, int n_in,
                              void* d_out, int out_size)
{
    const float* x       = (const float*)d_in[0];
    const float* t_w_in  = (const float*)d_in[1];
    const float* t_b_in  = (const float*)d_in[2];
    const float* t_w_out = (const float*)d_in[3];
    const float* t_b_out = (const float*)d_in[4];
    const float* s_w_in  = (const float*)d_in[5];
    const float* s_b_in  = (const float*)d_in[6];
    const float* s_w_out = (const float*)d_in[7];
    const float* s_b_out = (const float*)d_in[8];
    const float* gbias   = (const float*)d_in[9];
    const float* nt_g    = (const float*)d_in[10];
    const float* nt_b    = (const float*)d_in[11];
    const float* ns_g    = (const float*)d_in[12];
    const float* ns_b    = (const float*)d_in[13];
    const float* ff_w1   = (const float*)d_in[14];
    const float* ff_b1   = (const float*)d_in[15];
    const float* ff_w2   = (const float*)d_in[16];
    const float* ff_b2   = (const float*)d_in[17];
    const float* nf_g    = (const float*)d_in[18];
    const float* nf_b    = (const float*)d_in[19];
    float* out = (float*)d_out;

    float *qkv, *attn, *x1, *x2;
    bf16 *ahi, *alo, *bhi, *blo, *whi, *wlo;
    cudaGetSymbolAddress((void**)&qkv,  g_qkv);
    cudaGetSymbolAddress((void**)&attn, g_attn);
    cudaGetSymbolAddress((void**)&x1,   g_x1);
    cudaGetSymbolAddress((void**)&x2,   g_x2);
    cudaGetSymbolAddress((void**)&ahi,  g_ahi);
    cudaGetSymbolAddress((void**)&alo,  g_alo);
    cudaGetSymbolAddress((void**)&bhi,  g_bhi);
    cudaGetSymbolAddress((void**)&blo,  g_blo);
    cudaGetSymbolAddress((void**)&whi,  g_whi);
    cudaGetSymbolAddress((void**)&wlo,  g_wlo);

    cudaFuncSetAttribute(spatial_attn_kernel,
                         cudaFuncAttributeMaxDynamicSharedMemorySize, SP_SMEM);

    const int M = MTOK;                // 124800 = 975 * 128
    const int nMD = M * DD;            // 15,974,400

    // 1) temporal QKV: split x, t_w_in; GEMM -> qkv
    split_kernel<<<nMD/1024, 256>>>(x, ahi, alo, nMD);
    split_kernel<<<(D3*DD)/1024, 256>>>(t_w_in, whi, wlo, D3*DD);
    hmma_gemm<0><<<dim3(D3/128, M/128), 256>>>(
        ahi, alo, whi, wlo, t_b_in, nullptr, nullptr, nullptr,
        qkv, nullptr, nullptr, M, D3, DD);
    // 2) temporal attention
    temporal_attn_kernel<<<BB * NS, 256>>>(qkv, attn);
    // 3) temporal out-proj + residual(x) + LN -> x1
    split_kernel<<<nMD/1024, 256>>>(attn, ahi, alo, nMD);
    split_kernel<<<(DD*DD)/1024, 256>>>(t_w_out, whi, wlo, DD*DD);
    hmma_gemm<2><<<dim3(1, M/128), 256>>>(
        ahi, alo, whi, wlo, t_b_out, x, nt_g, nt_b,
        x1, nullptr, nullptr, M, DD, DD);
    // 4) spatial QKV
    split_kernel<<<nMD/1024, 256>>>(x1, ahi, alo, nMD);
    split_kernel<<<(D3*DD)/1024, 256>>>(s_w_in, whi, wlo, D3*DD);
    hmma_gemm<0><<<dim3(D3/128, M/128), 256>>>(
        ahi, alo, whi, wlo, s_b_in, nullptr, nullptr, nullptr,
        qkv, nullptr, nullptr, M, D3, DD);
    // 5) spatial attention
    spatial_attn_kernel<<<dim3(BB*TT, HH), SPT, SP_SMEM>>>(qkv, gbias, attn);
    // 6) spatial out-proj + residual(x1) + LN -> x2
    split_kernel<<<nMD/1024, 256>>>(attn, ahi, alo, nMD);
    split_kernel<<<(DD*DD)/1024, 256>>>(s_w_out, whi, wlo, DD*DD);
    hmma_gemm<2><<<dim3(1, M/128), 256>>>(
        ahi, alo, whi, wlo, s_b_out, x1, ns_g, ns_b,
        x2, nullptr, nullptr, M, DD, DD);
    // 7) FFN up + GELU -> bf16 split (bhi, blo)
    split_kernel<<<nMD/1024, 256>>>(x2, ahi, alo, nMD);
    split_kernel<<<(FF*DD)/1024, 256>>>(ff_w1, whi, wlo, FF*DD);
    hmma_gemm<1><<<dim3(FF/128, M/128), 256>>>(
        ahi, alo, whi, wlo, ff_b1, nullptr, nullptr, nullptr,
        nullptr, bhi, blo, M, FF, DD);
    // 8) FFN down + residual(x2) + LN -> out
    split_kernel<<<(DD*FF)/1024, 256>>>(ff_w2, whi, wlo, DD*FF);
    hmma_gemm<2><<<dim3(1, M/128), 256>>>(
        bhi, blo, whi, wlo, ff_b2, x2, nf_g, nf_b,
        out, nullptr, nullptr, M, DD, FF);
}